// round 1
// baseline (speedup 1.0000x reference)
#include <cuda_runtime.h>
#include <cuda_bf16.h>
#include <cstdint>

#define N_XROWS   50000
#define N_MOTIF   10000
#define N_TOT     60000
#define E_TOT     1920000
#define NHID      256
#define PAD_N     65536

// ---------------- device scratch (no allocs allowed) ----------------
__device__ int   g_cnt[N_TOT];
__device__ int   g_cur[N_TOT];
__device__ int   g_rowptr[N_TOT + 1];
__device__ int2  g_edges[E_TOT];                 // {col, val-bits} sorted by row
__device__ float g_support[(size_t)N_TOT * NHID];
__device__ float g_h1[(size_t)N_TOT * NHID];
__device__ float g_h2[(size_t)N_TOT * NHID];

// ---------------- f32x2 helpers ----------------
__device__ __forceinline__ unsigned long long pack2(float a, float b) {
    unsigned long long r;
    asm("mov.b64 %0, {%1, %2};" : "=l"(r) : "f"(a), "f"(b));
    return r;
}
__device__ __forceinline__ unsigned long long ffma2(unsigned long long a,
                                                    unsigned long long b,
                                                    unsigned long long c) {
    unsigned long long d;
    asm("fma.rn.f32x2 %0, %1, %2, %3;" : "=l"(d) : "l"(a), "l"(b), "l"(c));
    return d;
}
__device__ __forceinline__ float2 unpack2(unsigned long long v) {
    float2 r;
    asm("mov.b64 {%0, %1}, %2;" : "=f"(r.x), "=f"(r.y) : "l"(v));
    return r;
}

// ---------------- CSR build ----------------
__global__ void zero_cnt_kernel() {
    int i = blockIdx.x * 256 + threadIdx.x;
    if (i < N_TOT) { g_cnt[i] = 0; g_cur[i] = 0; }
}

__global__ void hist_kernel(const int* __restrict__ rows) {
    int i = blockIdx.x * 256 + threadIdx.x;
    if (i < E_TOT) atomicAdd(&g_cnt[rows[i]], 1);
}

__global__ void scan_kernel() {
    __shared__ int wsum[32];
    __shared__ int chunk_total;
    __shared__ int s_running;
    const int tid = threadIdx.x;
    const int lane = tid & 31, wid = tid >> 5;
    if (tid == 0) s_running = 0;
    __syncthreads();
    for (int base = 0; base < N_TOT; base += 1024) {
        int i = base + tid;
        int x = (i < N_TOT) ? g_cnt[i] : 0;
        int v = x;
        #pragma unroll
        for (int off = 1; off < 32; off <<= 1) {
            int u = __shfl_up_sync(0xffffffffu, v, off);
            if (lane >= off) v += u;
        }
        if (lane == 31) wsum[wid] = v;
        __syncthreads();
        if (wid == 0) {
            int w = wsum[lane];
            #pragma unroll
            for (int off = 1; off < 32; off <<= 1) {
                int u = __shfl_up_sync(0xffffffffu, w, off);
                if (lane >= off) w += u;
            }
            wsum[lane] = w;
            if (lane == 31) chunk_total = w;
        }
        __syncthreads();
        int warp_prefix = (wid == 0) ? 0 : wsum[wid - 1];
        int excl = s_running + warp_prefix + v - x;
        if (i < N_TOT) g_rowptr[i] = excl;
        __syncthreads();
        if (tid == 0) s_running += chunk_total;
        __syncthreads();
    }
    if (tid == 0) g_rowptr[N_TOT] = s_running;
}

__global__ void scatter_edges_kernel(const int* __restrict__ rows,
                                     const int* __restrict__ cols,
                                     const float* __restrict__ vals) {
    int i = blockIdx.x * 256 + threadIdx.x;
    if (i < E_TOT) {
        int r = rows[i];
        int pos = g_rowptr[r] + atomicAdd(&g_cur[r], 1);
        g_edges[pos] = make_int2(cols[i], __float_as_int(vals[i]));
    }
}

// ---------------- GEMM: C[M,256] = A[M,K] @ B[K,256] ----------------
// A is virtually concatenated: rows < split come from A0, rest from A1.
// BM=128, BN=64, BK=16, 256 threads, per-thread 8x4 microtile via f32x2
// (pairs along M).
__global__ void __launch_bounds__(256)
gemm_kernel(const float* __restrict__ A0, const float* __restrict__ A1,
            int split, int M, int K,
            const float* __restrict__ B, float* __restrict__ C) {
    __shared__ float As[16][128];   // [k][m] transposed
    __shared__ float Bs[16][64];    // [k][n]
    const int t   = threadIdx.x;
    const int tx  = t & 15;         // n group (4 cols)
    const int ty  = t >> 4;         // m group (8 rows)
    const int row0 = blockIdx.x * 128;
    const int col0 = blockIdx.y * 64;

    unsigned long long acc[4][4];
    const unsigned long long z = pack2(0.f, 0.f);
    #pragma unroll
    for (int p = 0; p < 4; p++)
        #pragma unroll
        for (int n = 0; n < 4; n++) acc[p][n] = z;

    for (int kb = 0; kb < K; kb += 16) {
        // load A tile 128x16 (two float4 per thread), store transposed
        #pragma unroll
        for (int j = 0; j < 2; j++) {
            int l = t * 2 + j;
            int m = l >> 2;     // 0..127
            int q = l & 3;      // k quarter
            int gm = row0 + m;
            float4 av = make_float4(0.f, 0.f, 0.f, 0.f);
            if (gm < M) {
                const float* Ap = (gm < split)
                    ? (A0 + (size_t)gm * K)
                    : (A1 + (size_t)(gm - split) * K);
                av = *(const float4*)(Ap + kb + q * 4);
            }
            As[q * 4 + 0][m] = av.x;
            As[q * 4 + 1][m] = av.y;
            As[q * 4 + 2][m] = av.z;
            As[q * 4 + 3][m] = av.w;
        }
        // load B tile 16x64 (one float4 per thread)
        {
            int k  = t >> 4;
            int n4 = (t & 15) * 4;
            float4 bv = *(const float4*)(B + (size_t)(kb + k) * 256 + col0 + n4);
            *(float4*)&Bs[k][n4] = bv;
        }
        __syncthreads();
        #pragma unroll
        for (int kk = 0; kk < 16; kk++) {
            const ulonglong2* ap = (const ulonglong2*)&As[kk][ty * 8];
            ulonglong2 A01 = ap[0];
            ulonglong2 A23 = ap[1];
            float4 bv = *(const float4*)&Bs[kk][tx * 4];
            unsigned long long bb0 = pack2(bv.x, bv.x);
            unsigned long long bb1 = pack2(bv.y, bv.y);
            unsigned long long bb2 = pack2(bv.z, bv.z);
            unsigned long long bb3 = pack2(bv.w, bv.w);
            acc[0][0] = ffma2(A01.x, bb0, acc[0][0]);
            acc[1][0] = ffma2(A01.y, bb0, acc[1][0]);
            acc[2][0] = ffma2(A23.x, bb0, acc[2][0]);
            acc[3][0] = ffma2(A23.y, bb0, acc[3][0]);
            acc[0][1] = ffma2(A01.x, bb1, acc[0][1]);
            acc[1][1] = ffma2(A01.y, bb1, acc[1][1]);
            acc[2][1] = ffma2(A23.x, bb1, acc[2][1]);
            acc[3][1] = ffma2(A23.y, bb1, acc[3][1]);
            acc[0][2] = ffma2(A01.x, bb2, acc[0][2]);
            acc[1][2] = ffma2(A01.y, bb2, acc[1][2]);
            acc[2][2] = ffma2(A23.x, bb2, acc[2][2]);
            acc[3][2] = ffma2(A23.y, bb2, acc[3][2]);
            acc[0][3] = ffma2(A01.x, bb3, acc[0][3]);
            acc[1][3] = ffma2(A01.y, bb3, acc[1][3]);
            acc[2][3] = ffma2(A23.x, bb3, acc[2][3]);
            acc[3][3] = ffma2(A23.y, bb3, acc[3][3]);
        }
        __syncthreads();
    }
    // store 8 rows x 4 cols
    #pragma unroll
    for (int p = 0; p < 4; p++) {
        float2 r0 = unpack2(acc[p][0]);
        float2 r1 = unpack2(acc[p][1]);
        float2 r2 = unpack2(acc[p][2]);
        float2 r3 = unpack2(acc[p][3]);
        int m0 = row0 + ty * 8 + p * 2;
        if (m0 < M) {
            float4 lo = make_float4(r0.x, r1.x, r2.x, r3.x);
            *(float4*)(C + (size_t)m0 * 256 + col0 + tx * 4) = lo;
        }
        if (m0 + 1 < M) {
            float4 hi = make_float4(r0.y, r1.y, r2.y, r3.y);
            *(float4*)(C + (size_t)(m0 + 1) * 256 + col0 + tx * 4) = hi;
        }
    }
}

// ---------------- SpMM: out[r] = relu(bias + sum_e val*support[col]) ----
__global__ void __launch_bounds__(64)
spmm_kernel(const float4* __restrict__ sup,
            const float4* __restrict__ bias,
            float4* __restrict__ out) {
    const int row = blockIdx.x;
    const int t   = threadIdx.x;       // 64 threads x float4 = 256 cols
    int s = g_rowptr[row];
    int e = g_rowptr[row + 1];
    float4 acc = make_float4(0.f, 0.f, 0.f, 0.f);
    int i = s;
    int2 ed = (i < e) ? __ldg(&g_edges[i]) : make_int2(0, 0);
    for (; i < e; i++) {
        int2 cur = ed;
        if (i + 1 < e) ed = __ldg(&g_edges[i + 1]);
        float v = __int_as_float(cur.y);
        float4 sv = __ldg(&sup[(size_t)cur.x * 64 + t]);
        acc.x = fmaf(v, sv.x, acc.x);
        acc.y = fmaf(v, sv.y, acc.y);
        acc.z = fmaf(v, sv.z, acc.z);
        acc.w = fmaf(v, sv.w, acc.w);
    }
    float4 b = __ldg(&bias[t]);
    float4 o;
    o.x = fmaxf(acc.x + b.x, 0.f);
    o.y = fmaxf(acc.y + b.y, 0.f);
    o.z = fmaxf(acc.z + b.z, 0.f);
    o.w = fmaxf(acc.w + b.w, 0.f);
    out[(size_t)row * 64 + t] = o;
}

// ---------------- output: zero + row scatter ----------------
__global__ void zero_out_kernel(float4* __restrict__ out, int n4) {
    int i = blockIdx.x * 256 + threadIdx.x;
    if (i < n4) out[i] = make_float4(0.f, 0.f, 0.f, 0.f);
}

__global__ void scatter_out_kernel(const float4* __restrict__ h,
                                   const int* __restrict__ pos,
                                   float4* __restrict__ out) {
    int idx = blockIdx.x * 256 + threadIdx.x;   // N_XROWS*64 total
    if (idx < N_XROWS * 64) {
        int i = idx >> 6;
        int t = idx & 63;
        out[(size_t)__ldg(&pos[i]) * 64 + t] = h[(size_t)i * 64 + t];
    }
}

// ---------------- launch ----------------
extern "C" void kernel_launch(void* const* d_in, const int* in_sizes, int n_in,
                              void* d_out, int out_size) {
    const float* x     = (const float*)d_in[0];
    const float* motif = (const float*)d_in[1];
    const int*   rows  = (const int*)d_in[2];
    const int*   cols  = (const int*)d_in[3];
    const float* vals  = (const float*)d_in[4];
    const int*   pos   = (const int*)d_in[5];
    // pad_n may or may not be materialized as a scalar input at index 6
    int wi = 6;
    if (n_in >= 13 && in_sizes[6] == 1) wi = 7;
    const float* w1 = (const float*)d_in[wi + 0];
    const float* b1 = (const float*)d_in[wi + 1];
    const float* w2 = (const float*)d_in[wi + 2];
    const float* b2 = (const float*)d_in[wi + 3];
    const float* w3 = (const float*)d_in[wi + 4];
    const float* b3 = (const float*)d_in[wi + 5];

    float *support, *h1, *h2;
    cudaGetSymbolAddress((void**)&support, g_support);
    cudaGetSymbolAddress((void**)&h1, g_h1);
    cudaGetSymbolAddress((void**)&h2, g_h2);

    // --- CSR build ---
    zero_cnt_kernel<<<(N_TOT + 255) / 256, 256>>>();
    hist_kernel<<<E_TOT / 256, 256>>>(rows);
    scan_kernel<<<1, 1024>>>();
    scatter_edges_kernel<<<E_TOT / 256, 256>>>(rows, cols, vals);

    dim3 gemm_grid((N_TOT + 127) / 128, 4);

    // --- layer 1 ---
    gemm_kernel<<<gemm_grid, 256>>>(x, motif, N_XROWS, N_TOT, 512, w1, support);
    spmm_kernel<<<N_TOT, 64>>>((const float4*)support, (const float4*)b1,
                               (float4*)h1);
    // --- layer 2 ---
    gemm_kernel<<<gemm_grid, 256>>>(h1, h1, N_TOT, N_TOT, 256, w2, support);
    spmm_kernel<<<N_TOT, 64>>>((const float4*)support, (const float4*)b2,
                               (float4*)h2);
    // --- layer 3 ---
    gemm_kernel<<<gemm_grid, 256>>>(h2, h2, N_TOT, N_TOT, 256, w3, support);
    spmm_kernel<<<N_TOT, 64>>>((const float4*)support, (const float4*)b3,
                               (float4*)h1);

    // --- output ---
    int n4 = out_size / 4;  // float4 count
    zero_out_kernel<<<(n4 + 255) / 256, 256>>>((float4*)d_out, n4);
    scatter_out_kernel<<<(N_XROWS * 64 + 255) / 256, 256>>>(
        (const float4*)h1, pos, (float4*)d_out);
}

// round 3
// speedup vs baseline: 1.1931x; 1.1931x over previous
#include <cuda_runtime.h>
#include <cuda_bf16.h>
#include <cstdint>

#define N_XROWS   50000
#define N_MOTIF   10000
#define N_TOT     60000
#define E_TOT     1920000
#define NHID      256
#define PAD_N     65536
#define M_PAD     60032          // 469 * 128

// ---------------- device scratch (no allocs allowed) ----------------
__device__ int   g_cnt[N_TOT];
__device__ int   g_cur[N_TOT];
__device__ int   g_rowptr[N_TOT + 1];
__device__ int2  g_edges[E_TOT];
__device__ float g_support[(size_t)N_TOT * NHID];
__device__ float g_h1[(size_t)N_TOT * NHID];
__device__ __nv_bfloat16 g_a2[(size_t)M_PAD * 1024];   // A operand, hi|lo split
__device__ __nv_bfloat16 g_b2[256 * 1024];             // B^T operand, hi|lo split

// ================= helpers =================
__device__ __forceinline__ uint32_t smem_u32(const void* p) {
    uint32_t a;
    asm("{ .reg .u64 t; cvta.to.shared.u64 t, %1; cvt.u32.u64 %0, t; }"
        : "=r"(a) : "l"(p));
    return a;
}
__device__ __forceinline__ void cp_async16(uint32_t dst, const void* src) {
    asm volatile("cp.async.cg.shared.global [%0], [%1], 16;"
                 :: "r"(dst), "l"(__cvta_generic_to_global(src)) : "memory");
}
#define CP_COMMIT() asm volatile("cp.async.commit_group;" ::: "memory")
#define CP_WAIT(n)  asm volatile("cp.async.wait_group %0;" :: "n"(n) : "memory")

__device__ __forceinline__ void mma16816(float* d, const uint32_t* a,
                                         const uint32_t* b) {
    asm volatile(
        "mma.sync.aligned.m16n8k16.row.col.f32.bf16.bf16.f32 "
        "{%0,%1,%2,%3}, {%4,%5,%6,%7}, {%8,%9}, {%0,%1,%2,%3};"
        : "+f"(d[0]), "+f"(d[1]), "+f"(d[2]), "+f"(d[3])
        : "r"(a[0]), "r"(a[1]), "r"(a[2]), "r"(a[3]), "r"(b[0]), "r"(b[1]));
}

// ---------------- CSR build ----------------
__global__ void zero_cnt_kernel() {
    int i = blockIdx.x * 256 + threadIdx.x;
    if (i < N_TOT) { g_cnt[i] = 0; g_cur[i] = 0; }
}
__global__ void hist_kernel(const int* __restrict__ rows) {
    int i = blockIdx.x * 256 + threadIdx.x;
    if (i < E_TOT) atomicAdd(&g_cnt[rows[i]], 1);
}
__global__ void scan_kernel() {
    __shared__ int wsum[32];
    __shared__ int chunk_total;
    __shared__ int s_running;
    const int tid = threadIdx.x;
    const int lane = tid & 31, wid = tid >> 5;
    if (tid == 0) s_running = 0;
    __syncthreads();
    for (int base = 0; base < N_TOT; base += 1024) {
        int i = base + tid;
        int x = (i < N_TOT) ? g_cnt[i] : 0;
        int v = x;
        #pragma unroll
        for (int off = 1; off < 32; off <<= 1) {
            int u = __shfl_up_sync(0xffffffffu, v, off);
            if (lane >= off) v += u;
        }
        if (lane == 31) wsum[wid] = v;
        __syncthreads();
        if (wid == 0) {
            int w = wsum[lane];
            #pragma unroll
            for (int off = 1; off < 32; off <<= 1) {
                int u = __shfl_up_sync(0xffffffffu, w, off);
                if (lane >= off) w += u;
            }
            wsum[lane] = w;
            if (lane == 31) chunk_total = w;
        }
        __syncthreads();
        int warp_prefix = (wid == 0) ? 0 : wsum[wid - 1];
        int excl = s_running + warp_prefix + v - x;
        if (i < N_TOT) g_rowptr[i] = excl;
        __syncthreads();
        if (tid == 0) s_running += chunk_total;
        __syncthreads();
    }
    if (tid == 0) g_rowptr[N_TOT] = s_running;
}
__global__ void scatter_edges_kernel(const int* __restrict__ rows,
                                     const int* __restrict__ cols,
                                     const float* __restrict__ vals) {
    int i = blockIdx.x * 256 + threadIdx.x;
    if (i < E_TOT) {
        int r = rows[i];
        int pos = g_rowptr[r] + atomicAdd(&g_cur[r], 1);
        g_edges[pos] = make_int2(cols[i], __float_as_int(vals[i]));
    }
}

// ---------------- bf16 split conversions ----------------
__device__ __forceinline__ uint64_t pack4(__nv_bfloat16 a, __nv_bfloat16 b,
                                          __nv_bfloat16 c, __nv_bfloat16 d) {
    __nv_bfloat162 p0 = __halves2bfloat162(a, b);
    __nv_bfloat162 p1 = __halves2bfloat162(c, d);
    uint32_t u0 = *(uint32_t*)&p0;
    uint32_t u1 = *(uint32_t*)&p1;
    return (uint64_t)u0 | ((uint64_t)u1 << 32);
}

// x/motif [60000,512] fp32 -> g_a2 [m][0..511]=hi, [512..1023]=lo
__global__ void convertA_kernel(const float* __restrict__ x,
                                const float* __restrict__ motif,
                                __nv_bfloat16* __restrict__ out) {
    int idx = blockIdx.x * 256 + threadIdx.x;      // N_TOT*128 threads
    if (idx >= N_TOT * 128) return;
    int m  = idx >> 7;
    int kq = (idx & 127) << 2;
    const float* src = (m < N_XROWS)
        ? x + (size_t)m * 512 + kq
        : motif + (size_t)(m - N_XROWS) * 512 + kq;
    float4 v = *(const float4*)src;
    __nv_bfloat16 h0 = __float2bfloat16(v.x), h1 = __float2bfloat16(v.y);
    __nv_bfloat16 h2 = __float2bfloat16(v.z), h3 = __float2bfloat16(v.w);
    __nv_bfloat16 l0 = __float2bfloat16(v.x - __bfloat162float(h0));
    __nv_bfloat16 l1 = __float2bfloat16(v.y - __bfloat162float(h1));
    __nv_bfloat16 l2 = __float2bfloat16(v.z - __bfloat162float(h2));
    __nv_bfloat16 l3 = __float2bfloat16(v.w - __bfloat162float(h3));
    size_t base = (size_t)m * 1024 + kq;
    *(uint64_t*)(out + base)       = pack4(h0, h1, h2, h3);
    *(uint64_t*)(out + base + 512) = pack4(l0, l1, l2, l3);
}

// B [K,N=256] fp32 -> g_b2 [n][0..K-1]=hi, [K..2K-1]=lo  (B^T, K-major)
__global__ void convertB_kernel(const float* __restrict__ B, int K,
                                __nv_bfloat16* __restrict__ out) {
    int idx = blockIdx.x * 256 + threadIdx.x;    // K*256 threads
    if (idx >= K * 256) return;
    int k = idx >> 8;
    int n = idx & 255;
    float v = B[idx];
    __nv_bfloat16 h = __float2bfloat16(v);
    __nv_bfloat16 l = __float2bfloat16(v - __bfloat162float(h));
    out[(size_t)n * 2 * K + k]     = h;
    out[(size_t)n * 2 * K + K + k] = l;
}

// ---------------- HMMA GEMM: C[M,256] = A2 @ B2^T (bf16 3-pass) ----
// CTA tile 128x128, BK=32, 8 warps (4 along M, 2 along N), 3-stage cp.async.
#define SA 40                          // padded SMEM row stride (elements)
#define STAGE_ELEMS (2 * 128 * SA)     // A tile + B tile
#define GEMM_SMEM   (3 * STAGE_ELEMS * 2)

__global__ void __launch_bounds__(256, 1)
hmma_gemm_kernel(const __nv_bfloat16* __restrict__ A2,
                 const __nv_bfloat16* __restrict__ B2,
                 float* __restrict__ C, int K, int M) {
    extern __shared__ __nv_bfloat16 sm[];
    const int t    = threadIdx.x;
    const int lane = t & 31, wid = t >> 5;
    const int wm   = wid & 3, wn = wid >> 2;
    const int gid  = lane >> 2, tid4 = lane & 3;
    const int row0 = blockIdx.x * 128;
    const int col0 = blockIdx.y * 128;
    const int stride = 2 * K;
    const int KB = K >> 5;            // 32-wide chunks per pass
    const int CC = 3 * KB;            // hi*hi, hi*lo, lo*hi

    float acc[2][8][4];
    #pragma unroll
    for (int mi = 0; mi < 2; mi++)
        #pragma unroll
        for (int ni = 0; ni < 8; ni++)
            #pragma unroll
            for (int q = 0; q < 4; q++) acc[mi][ni][q] = 0.f;

    // chunk -> (aoff, boff) in elements
    auto offs = [&](int c, int& aoff, int& boff) {
        int pass = c / KB, kb = c - pass * KB;
        aoff = (pass == 2 ? K : 0) + (kb << 5);
        boff = (pass == 1 ? K : 0) + (kb << 5);
    };
    auto load_chunk = [&](int stage, int aoff, int boff) {
        __nv_bfloat16* s  = sm + stage * STAGE_ELEMS;
        __nv_bfloat16* sB = s + 128 * SA;
        #pragma unroll
        for (int j = 0; j < 2; j++) {
            int u = j * 256 + t;
            int r = u >> 2, q = u & 3;
            cp_async16(smem_u32(s + r * SA + q * 8),
                       A2 + (size_t)(row0 + r) * stride + aoff + q * 8);
        }
        #pragma unroll
        for (int j = 0; j < 2; j++) {
            int u = j * 256 + t;
            int r = u >> 2, q = u & 3;
            cp_async16(smem_u32(sB + r * SA + q * 8),
                       B2 + (size_t)(col0 + r) * stride + boff + q * 8);
        }
        CP_COMMIT();
    };

    {
        int a0, b0, a1, b1;
        offs(0, a0, b0); load_chunk(0, a0, b0);
        offs(1, a1, b1); load_chunk(1, a1, b1);
    }

    for (int c = 0; c < CC; c++) {
        if (c < CC - 1) CP_WAIT(1); else CP_WAIT(0);
        __syncthreads();
        if (c + 2 < CC) {
            int ao, bo;
            offs(c + 2, ao, bo);
            load_chunk((c + 2) % 3, ao, bo);
        }
        const __nv_bfloat16* s  = sm + (c % 3) * STAGE_ELEMS;
        const __nv_bfloat16* sB = s + 128 * SA;
        #pragma unroll
        for (int ks = 0; ks < 2; ks++) {
            uint32_t a[2][4], b[8][2];
            #pragma unroll
            for (int mi = 0; mi < 2; mi++) {
                int r0 = wm * 32 + mi * 16 + gid;
                int kc = ks * 16 + tid4 * 2;
                a[mi][0] = *(const uint32_t*)(s + (size_t)r0 * SA + kc);
                a[mi][1] = *(const uint32_t*)(s + (size_t)(r0 + 8) * SA + kc);
                a[mi][2] = *(const uint32_t*)(s + (size_t)r0 * SA + kc + 8);
                a[mi][3] = *(const uint32_t*)(s + (size_t)(r0 + 8) * SA + kc + 8);
            }
            #pragma unroll
            for (int ni = 0; ni < 8; ni++) {
                int n0 = wn * 64 + ni * 8 + gid;
                int kc = ks * 16 + tid4 * 2;
                b[ni][0] = *(const uint32_t*)(sB + (size_t)n0 * SA + kc);
                b[ni][1] = *(const uint32_t*)(sB + (size_t)n0 * SA + kc + 8);
            }
            #pragma unroll
            for (int mi = 0; mi < 2; mi++)
                #pragma unroll
                for (int ni = 0; ni < 8; ni++)
                    mma16816(acc[mi][ni], a[mi], b[ni]);
        }
    }

    // epilogue
    #pragma unroll
    for (int mi = 0; mi < 2; mi++) {
        int r = row0 + wm * 32 + mi * 16 + gid;
        #pragma unroll
        for (int ni = 0; ni < 8; ni++) {
            int cidx = col0 + wn * 64 + ni * 8 + tid4 * 2;
            if (r < M)
                *(float2*)(C + (size_t)r * 256 + cidx) =
                    make_float2(acc[mi][ni][0], acc[mi][ni][1]);
            if (r + 8 < M)
                *(float2*)(C + (size_t)(r + 8) * 256 + cidx) =
                    make_float2(acc[mi][ni][2], acc[mi][ni][3]);
        }
    }
}

// ---------------- SpMM: relu(bias + sum val*support[col]) --------------
__global__ void __launch_bounds__(64)
spmm_bf16_kernel(const float4* __restrict__ sup,
                 const float4* __restrict__ bias,
                 __nv_bfloat16* __restrict__ a2) {
    const int row = blockIdx.x;
    const int t   = threadIdx.x;
    int s = g_rowptr[row];
    int e = g_rowptr[row + 1];
    float4 acc = make_float4(0.f, 0.f, 0.f, 0.f);
    int i = s;
    int2 ed = (i < e) ? __ldg(&g_edges[i]) : make_int2(0, 0);
    for (; i < e; i++) {
        int2 cur = ed;
        if (i + 1 < e) ed = __ldg(&g_edges[i + 1]);
        float v = __int_as_float(cur.y);
        float4 sv = __ldg(&sup[(size_t)cur.x * 64 + t]);
        acc.x = fmaf(v, sv.x, acc.x);
        acc.y = fmaf(v, sv.y, acc.y);
        acc.z = fmaf(v, sv.z, acc.z);
        acc.w = fmaf(v, sv.w, acc.w);
    }
    float4 b = __ldg(&bias[t]);
    float ox = fmaxf(acc.x + b.x, 0.f);
    float oy = fmaxf(acc.y + b.y, 0.f);
    float oz = fmaxf(acc.z + b.z, 0.f);
    float ow = fmaxf(acc.w + b.w, 0.f);
    __nv_bfloat16 h0 = __float2bfloat16(ox), h1 = __float2bfloat16(oy);
    __nv_bfloat16 h2 = __float2bfloat16(oz), h3 = __float2bfloat16(ow);
    __nv_bfloat16 l0 = __float2bfloat16(ox - __bfloat162float(h0));
    __nv_bfloat16 l1 = __float2bfloat16(oy - __bfloat162float(h1));
    __nv_bfloat16 l2 = __float2bfloat16(oz - __bfloat162float(h2));
    __nv_bfloat16 l3 = __float2bfloat16(ow - __bfloat162float(h3));
    size_t base = (size_t)row * 512 + t * 4;
    *(uint64_t*)(a2 + base)       = pack4(h0, h1, h2, h3);
    *(uint64_t*)(a2 + base + 256) = pack4(l0, l1, l2, l3);
}

__global__ void __launch_bounds__(64)
spmm_f32_kernel(const float4* __restrict__ sup,
                const float4* __restrict__ bias,
                float4* __restrict__ out) {
    const int row = blockIdx.x;
    const int t   = threadIdx.x;
    int s = g_rowptr[row];
    int e = g_rowptr[row + 1];
    float4 acc = make_float4(0.f, 0.f, 0.f, 0.f);
    int i = s;
    int2 ed = (i < e) ? __ldg(&g_edges[i]) : make_int2(0, 0);
    for (; i < e; i++) {
        int2 cur = ed;
        if (i + 1 < e) ed = __ldg(&g_edges[i + 1]);
        float v = __int_as_float(cur.y);
        float4 sv = __ldg(&sup[(size_t)cur.x * 64 + t]);
        acc.x = fmaf(v, sv.x, acc.x);
        acc.y = fmaf(v, sv.y, acc.y);
        acc.z = fmaf(v, sv.z, acc.z);
        acc.w = fmaf(v, sv.w, acc.w);
    }
    float4 b = __ldg(&bias[t]);
    float4 o;
    o.x = fmaxf(acc.x + b.x, 0.f);
    o.y = fmaxf(acc.y + b.y, 0.f);
    o.z = fmaxf(acc.z + b.z, 0.f);
    o.w = fmaxf(acc.w + b.w, 0.f);
    out[(size_t)row * 64 + t] = o;
}

// ---------------- output: zero + row scatter ----------------
__global__ void zero_out_kernel(float4* __restrict__ out, int n4) {
    int i = blockIdx.x * 256 + threadIdx.x;
    if (i < n4) out[i] = make_float4(0.f, 0.f, 0.f, 0.f);
}
__global__ void scatter_out_kernel(const float4* __restrict__ h,
                                   const int* __restrict__ pos,
                                   float4* __restrict__ out) {
    int idx = blockIdx.x * 256 + threadIdx.x;
    if (idx < N_XROWS * 64) {
        int i = idx >> 6;
        int t = idx & 63;
        out[(size_t)__ldg(&pos[i]) * 64 + t] = h[(size_t)i * 64 + t];
    }
}

// ---------------- launch ----------------
extern "C" void kernel_launch(void* const* d_in, const int* in_sizes, int n_in,
                              void* d_out, int out_size) {
    const float* x     = (const float*)d_in[0];
    const float* motif = (const float*)d_in[1];
    const int*   rows  = (const int*)d_in[2];
    const int*   cols  = (const int*)d_in[3];
    const float* vals  = (const float*)d_in[4];
    const int*   pos   = (const int*)d_in[5];
    int wi = 6;
    if (n_in >= 13 && in_sizes[6] == 1) wi = 7;
    const float* w1 = (const float*)d_in[wi + 0];
    const float* b1 = (const float*)d_in[wi + 1];
    const float* w2 = (const float*)d_in[wi + 2];
    const float* b2 = (const float*)d_in[wi + 3];
    const float* w3 = (const float*)d_in[wi + 4];
    const float* b3 = (const float*)d_in[wi + 5];

    float *support, *h1;
    __nv_bfloat16 *a2, *bt2;
    cudaGetSymbolAddress((void**)&support, g_support);
    cudaGetSymbolAddress((void**)&h1, g_h1);
    cudaGetSymbolAddress((void**)&a2, g_a2);
    cudaGetSymbolAddress((void**)&bt2, g_b2);

    cudaFuncSetAttribute(hmma_gemm_kernel,
                         cudaFuncAttributeMaxDynamicSharedMemorySize, GEMM_SMEM);

    // --- CSR build ---
    zero_cnt_kernel<<<(N_TOT + 255) / 256, 256>>>();
    hist_kernel<<<E_TOT / 256, 256>>>(rows);
    scan_kernel<<<1, 1024>>>();
    scatter_edges_kernel<<<E_TOT / 256, 256>>>(rows, cols, vals);

    const dim3 gemm_grid(M_PAD / 128, 2);   // 469 x 2

    // --- layer 1 (K=512) ---
    convertA_kernel<<<(N_TOT * 128) / 256, 256>>>(x, motif, a2);
    convertB_kernel<<<512, 256>>>(w1, 512, bt2);
    hmma_gemm_kernel<<<gemm_grid, 256, GEMM_SMEM>>>(a2, bt2, support, 512, N_TOT);
    spmm_bf16_kernel<<<N_TOT, 64>>>((const float4*)support, (const float4*)b1, a2);

    // --- layer 2 (K=256) ---
    convertB_kernel<<<256, 256>>>(w2, 256, bt2);
    hmma_gemm_kernel<<<gemm_grid, 256, GEMM_SMEM>>>(a2, bt2, support, 256, N_TOT);
    spmm_bf16_kernel<<<N_TOT, 64>>>((const float4*)support, (const float4*)b2, a2);

    // --- layer 3 (K=256) ---
    convertB_kernel<<<256, 256>>>(w3, 256, bt2);
    hmma_gemm_kernel<<<gemm_grid, 256, GEMM_SMEM>>>(a2, bt2, support, 256, N_TOT);
    spmm_f32_kernel<<<N_TOT, 64>>>((const float4*)support, (const float4*)b3,
                                   (float4*)h1);

    // --- output ---
    int n4 = out_size / 4;
    zero_out_kernel<<<(n4 + 255) / 256, 256>>>((float4*)d_out, n4);
    scatter_out_kernel<<<(N_XROWS * 64 + 255) / 256, 256>>>(
        (const float4*)h1, pos, (float4*)d_out);
}

// round 4
// speedup vs baseline: 1.2397x; 1.0391x over previous
#include <cuda_runtime.h>
#include <cuda_bf16.h>
#include <cuda_fp16.h>
#include <cstdint>

#define N_XROWS   50000
#define N_MOTIF   10000
#define N_TOT     60000
#define E_TOT     1920000
#define NHID      256
#define PAD_N     65536
#define M_PAD     60032          // 469 * 128

// ---------------- device scratch (no allocs allowed) ----------------
__device__ int   g_cnt[N_TOT];
__device__ int   g_cur[N_TOT];
__device__ int   g_rowptr[N_TOT + 1];
__device__ int2  g_edges[E_TOT];
__device__ __half g_support[(size_t)N_TOT * NHID];     // fp16 support
__device__ float g_h1[(size_t)N_TOT * NHID];
__device__ __nv_bfloat16 g_a2[(size_t)M_PAD * 1024];   // A operand, hi|lo split
__device__ __nv_bfloat16 g_b2[256 * 1024];             // B^T operand, hi|lo split

// ================= helpers =================
__device__ __forceinline__ uint32_t smem_u32(const void* p) {
    uint32_t a;
    asm("{ .reg .u64 t; cvta.to.shared.u64 t, %1; cvt.u32.u64 %0, t; }"
        : "=r"(a) : "l"(p));
    return a;
}
__device__ __forceinline__ void cp_async16(uint32_t dst, const void* src) {
    asm volatile("cp.async.cg.shared.global [%0], [%1], 16;"
                 :: "r"(dst), "l"(__cvta_generic_to_global(src)) : "memory");
}
#define CP_COMMIT() asm volatile("cp.async.commit_group;" ::: "memory")
#define CP_WAIT(n)  asm volatile("cp.async.wait_group %0;" :: "n"(n) : "memory")

__device__ __forceinline__ void mma16816(float* d, const uint32_t* a,
                                         const uint32_t* b) {
    asm volatile(
        "mma.sync.aligned.m16n8k16.row.col.f32.bf16.bf16.f32 "
        "{%0,%1,%2,%3}, {%4,%5,%6,%7}, {%8,%9}, {%0,%1,%2,%3};"
        : "+f"(d[0]), "+f"(d[1]), "+f"(d[2]), "+f"(d[3])
        : "r"(a[0]), "r"(a[1]), "r"(a[2]), "r"(a[3]), "r"(b[0]), "r"(b[1]));
}

// ---------------- CSR build ----------------
__global__ void zero_cnt_kernel() {
    int i = blockIdx.x * 256 + threadIdx.x;
    if (i < N_TOT) { g_cnt[i] = 0; g_cur[i] = 0; }
}
__global__ void hist_kernel(const int* __restrict__ rows) {
    int i = blockIdx.x * 256 + threadIdx.x;
    if (i < E_TOT) atomicAdd(&g_cnt[rows[i]], 1);
}
__global__ void scan_kernel() {
    __shared__ int wsum[32];
    __shared__ int chunk_total;
    __shared__ int s_running;
    const int tid = threadIdx.x;
    const int lane = tid & 31, wid = tid >> 5;
    if (tid == 0) s_running = 0;
    __syncthreads();
    for (int base = 0; base < N_TOT; base += 1024) {
        int i = base + tid;
        int x = (i < N_TOT) ? g_cnt[i] : 0;
        int v = x;
        #pragma unroll
        for (int off = 1; off < 32; off <<= 1) {
            int u = __shfl_up_sync(0xffffffffu, v, off);
            if (lane >= off) v += u;
        }
        if (lane == 31) wsum[wid] = v;
        __syncthreads();
        if (wid == 0) {
            int w = wsum[lane];
            #pragma unroll
            for (int off = 1; off < 32; off <<= 1) {
                int u = __shfl_up_sync(0xffffffffu, w, off);
                if (lane >= off) w += u;
            }
            wsum[lane] = w;
            if (lane == 31) chunk_total = w;
        }
        __syncthreads();
        int warp_prefix = (wid == 0) ? 0 : wsum[wid - 1];
        int excl = s_running + warp_prefix + v - x;
        if (i < N_TOT) g_rowptr[i] = excl;
        __syncthreads();
        if (tid == 0) s_running += chunk_total;
        __syncthreads();
    }
    if (tid == 0) g_rowptr[N_TOT] = s_running;
}
__global__ void scatter_edges_kernel(const int* __restrict__ rows,
                                     const int* __restrict__ cols,
                                     const float* __restrict__ vals) {
    int i = blockIdx.x * 256 + threadIdx.x;
    if (i < E_TOT) {
        int r = rows[i];
        int pos = g_rowptr[r] + atomicAdd(&g_cur[r], 1);
        g_edges[pos] = make_int2(cols[i], __float_as_int(vals[i]));
    }
}

// ---------------- bf16 split conversions ----------------
__device__ __forceinline__ uint64_t pack4(__nv_bfloat16 a, __nv_bfloat16 b,
                                          __nv_bfloat16 c, __nv_bfloat16 d) {
    __nv_bfloat162 p0 = __halves2bfloat162(a, b);
    __nv_bfloat162 p1 = __halves2bfloat162(c, d);
    uint32_t u0 = *(uint32_t*)&p0;
    uint32_t u1 = *(uint32_t*)&p1;
    return (uint64_t)u0 | ((uint64_t)u1 << 32);
}

// x/motif [60000,512] fp32 -> g_a2 [m][0..511]=hi, [512..1023]=lo
__global__ void convertA_kernel(const float* __restrict__ x,
                                const float* __restrict__ motif,
                                __nv_bfloat16* __restrict__ out) {
    int idx = blockIdx.x * 256 + threadIdx.x;      // N_TOT*128 threads
    if (idx >= N_TOT * 128) return;
    int m  = idx >> 7;
    int kq = (idx & 127) << 2;
    const float* src = (m < N_XROWS)
        ? x + (size_t)m * 512 + kq
        : motif + (size_t)(m - N_XROWS) * 512 + kq;
    float4 v = *(const float4*)src;
    __nv_bfloat16 h0 = __float2bfloat16(v.x), h1 = __float2bfloat16(v.y);
    __nv_bfloat16 h2 = __float2bfloat16(v.z), h3 = __float2bfloat16(v.w);
    __nv_bfloat16 l0 = __float2bfloat16(v.x - __bfloat162float(h0));
    __nv_bfloat16 l1 = __float2bfloat16(v.y - __bfloat162float(h1));
    __nv_bfloat16 l2 = __float2bfloat16(v.z - __bfloat162float(h2));
    __nv_bfloat16 l3 = __float2bfloat16(v.w - __bfloat162float(h3));
    size_t base = (size_t)m * 1024 + kq;
    *(uint64_t*)(out + base)       = pack4(h0, h1, h2, h3);
    *(uint64_t*)(out + base + 512) = pack4(l0, l1, l2, l3);
}

// B [K,N=256] fp32 -> g_b2 [n][0..K-1]=hi, [K..2K-1]=lo  (B^T, K-major)
__global__ void convertB_kernel(const float* __restrict__ B, int K,
                                __nv_bfloat16* __restrict__ out) {
    int idx = blockIdx.x * 256 + threadIdx.x;    // K*256 threads
    if (idx >= K * 256) return;
    int k = idx >> 8;
    int n = idx & 255;
    float v = B[idx];
    __nv_bfloat16 h = __float2bfloat16(v);
    __nv_bfloat16 l = __float2bfloat16(v - __bfloat162float(h));
    out[(size_t)n * 2 * K + k]     = h;
    out[(size_t)n * 2 * K + K + k] = l;
}

// ---------------- HMMA GEMM: C[M,256] = A2 @ B2^T (bf16 3-pass) ----
// CTA tile 128x128, BK=32, 8 warps (4 along M, 2 along N), 3-stage cp.async.
// Epilogue writes fp16 support.
#define SA 40                          // padded SMEM row stride (elements)
#define STAGE_ELEMS (2 * 128 * SA)     // A tile + B tile
#define GEMM_SMEM   (3 * STAGE_ELEMS * 2)

__global__ void __launch_bounds__(256, 1)
hmma_gemm_kernel(const __nv_bfloat16* __restrict__ A2,
                 const __nv_bfloat16* __restrict__ B2,
                 __half* __restrict__ C, int K, int M) {
    extern __shared__ __nv_bfloat16 sm[];
    const int t    = threadIdx.x;
    const int lane = t & 31, wid = t >> 5;
    const int wm   = wid & 3, wn = wid >> 2;
    const int gid  = lane >> 2, tid4 = lane & 3;
    const int row0 = blockIdx.x * 128;
    const int col0 = blockIdx.y * 128;
    const int stride = 2 * K;
    const int KB = K >> 5;            // 32-wide chunks per pass
    const int CC = 3 * KB;            // hi*hi, hi*lo, lo*hi

    float acc[2][8][4];
    #pragma unroll
    for (int mi = 0; mi < 2; mi++)
        #pragma unroll
        for (int ni = 0; ni < 8; ni++)
            #pragma unroll
            for (int q = 0; q < 4; q++) acc[mi][ni][q] = 0.f;

    auto offs = [&](int c, int& aoff, int& boff) {
        int pass = c / KB, kb = c - pass * KB;
        aoff = (pass == 2 ? K : 0) + (kb << 5);
        boff = (pass == 1 ? K : 0) + (kb << 5);
    };
    auto load_chunk = [&](int stage, int aoff, int boff) {
        __nv_bfloat16* s  = sm + stage * STAGE_ELEMS;
        __nv_bfloat16* sB = s + 128 * SA;
        #pragma unroll
        for (int j = 0; j < 2; j++) {
            int u = j * 256 + t;
            int r = u >> 2, q = u & 3;
            cp_async16(smem_u32(s + r * SA + q * 8),
                       A2 + (size_t)(row0 + r) * stride + aoff + q * 8);
        }
        #pragma unroll
        for (int j = 0; j < 2; j++) {
            int u = j * 256 + t;
            int r = u >> 2, q = u & 3;
            cp_async16(smem_u32(sB + r * SA + q * 8),
                       B2 + (size_t)(col0 + r) * stride + boff + q * 8);
        }
        CP_COMMIT();
    };

    {
        int a0, b0, a1, b1;
        offs(0, a0, b0); load_chunk(0, a0, b0);
        offs(1, a1, b1); load_chunk(1, a1, b1);
    }

    for (int c = 0; c < CC; c++) {
        if (c < CC - 1) CP_WAIT(1); else CP_WAIT(0);
        __syncthreads();
        if (c + 2 < CC) {
            int ao, bo;
            offs(c + 2, ao, bo);
            load_chunk((c + 2) % 3, ao, bo);
        }
        const __nv_bfloat16* s  = sm + (c % 3) * STAGE_ELEMS;
        const __nv_bfloat16* sB = s + 128 * SA;
        #pragma unroll
        for (int ks = 0; ks < 2; ks++) {
            uint32_t a[2][4], b[8][2];
            #pragma unroll
            for (int mi = 0; mi < 2; mi++) {
                int r0 = wm * 32 + mi * 16 + gid;
                int kc = ks * 16 + tid4 * 2;
                a[mi][0] = *(const uint32_t*)(s + (size_t)r0 * SA + kc);
                a[mi][1] = *(const uint32_t*)(s + (size_t)(r0 + 8) * SA + kc);
                a[mi][2] = *(const uint32_t*)(s + (size_t)r0 * SA + kc + 8);
                a[mi][3] = *(const uint32_t*)(s + (size_t)(r0 + 8) * SA + kc + 8);
            }
            #pragma unroll
            for (int ni = 0; ni < 8; ni++) {
                int n0 = wn * 64 + ni * 8 + gid;
                int kc = ks * 16 + tid4 * 2;
                b[ni][0] = *(const uint32_t*)(sB + (size_t)n0 * SA + kc);
                b[ni][1] = *(const uint32_t*)(sB + (size_t)n0 * SA + kc + 8);
            }
            #pragma unroll
            for (int mi = 0; mi < 2; mi++)
                #pragma unroll
                for (int ni = 0; ni < 8; ni++)
                    mma16816(acc[mi][ni], a[mi], b[ni]);
        }
    }

    // epilogue -> fp16
    #pragma unroll
    for (int mi = 0; mi < 2; mi++) {
        int r = row0 + wm * 32 + mi * 16 + gid;
        #pragma unroll
        for (int ni = 0; ni < 8; ni++) {
            int cidx = col0 + wn * 64 + ni * 8 + tid4 * 2;
            if (r < M)
                *(__half2*)(C + (size_t)r * 256 + cidx) =
                    __floats2half2_rn(acc[mi][ni][0], acc[mi][ni][1]);
            if (r + 8 < M)
                *(__half2*)(C + (size_t)(r + 8) * 256 + cidx) =
                    __floats2half2_rn(acc[mi][ni][2], acc[mi][ni][3]);
        }
    }
}

// ---------------- SpMM: relu(bias + sum val*support_fp16[col]) ----------
// 64 threads/row; thread t covers cols [4t, 4t+4): one uint2 (4 halfs).
__device__ __forceinline__ float4 spmm_row(const uint2* __restrict__ sup2,
                                           int row, int t) {
    int s = g_rowptr[row];
    int e = g_rowptr[row + 1];
    float4 acc = make_float4(0.f, 0.f, 0.f, 0.f);
    int i = s;
    int2 ed = (i < e) ? __ldg(&g_edges[i]) : make_int2(0, 0);
    for (; i < e; i++) {
        int2 cur = ed;
        if (i + 1 < e) ed = __ldg(&g_edges[i + 1]);
        float v = __int_as_float(cur.y);
        uint2 raw = __ldg(&sup2[(size_t)cur.x * 64 + t]);
        float2 f0 = __half22float2(*(__half2*)&raw.x);
        float2 f1 = __half22float2(*(__half2*)&raw.y);
        acc.x = fmaf(v, f0.x, acc.x);
        acc.y = fmaf(v, f0.y, acc.y);
        acc.z = fmaf(v, f1.x, acc.z);
        acc.w = fmaf(v, f1.y, acc.w);
    }
    return acc;
}

__global__ void __launch_bounds__(64)
spmm_bf16_kernel(const uint2* __restrict__ sup2,
                 const float4* __restrict__ bias,
                 __nv_bfloat16* __restrict__ a2) {
    const int row = blockIdx.x;
    const int t   = threadIdx.x;
    float4 acc = spmm_row(sup2, row, t);
    float4 b = __ldg(&bias[t]);
    float ox = fmaxf(acc.x + b.x, 0.f);
    float oy = fmaxf(acc.y + b.y, 0.f);
    float oz = fmaxf(acc.z + b.z, 0.f);
    float ow = fmaxf(acc.w + b.w, 0.f);
    __nv_bfloat16 h0 = __float2bfloat16(ox), h1 = __float2bfloat16(oy);
    __nv_bfloat16 h2 = __float2bfloat16(oz), h3 = __float2bfloat16(ow);
    __nv_bfloat16 l0 = __float2bfloat16(ox - __bfloat162float(h0));
    __nv_bfloat16 l1 = __float2bfloat16(oy - __bfloat162float(h1));
    __nv_bfloat16 l2 = __float2bfloat16(oz - __bfloat162float(h2));
    __nv_bfloat16 l3 = __float2bfloat16(ow - __bfloat162float(h3));
    size_t base = (size_t)row * 512 + t * 4;
    *(uint64_t*)(a2 + base)       = pack4(h0, h1, h2, h3);
    *(uint64_t*)(a2 + base + 256) = pack4(l0, l1, l2, l3);
}

__global__ void __launch_bounds__(64)
spmm_f32_kernel(const uint2* __restrict__ sup2,
                const float4* __restrict__ bias,
                float4* __restrict__ out) {
    const int row = blockIdx.x;
    const int t   = threadIdx.x;
    float4 acc = spmm_row(sup2, row, t);
    float4 b = __ldg(&bias[t]);
    float4 o;
    o.x = fmaxf(acc.x + b.x, 0.f);
    o.y = fmaxf(acc.y + b.y, 0.f);
    o.z = fmaxf(acc.z + b.z, 0.f);
    o.w = fmaxf(acc.w + b.w, 0.f);
    out[(size_t)row * 64 + t] = o;
}

// ---------------- output: zero + row scatter ----------------
__global__ void zero_out_kernel(float4* __restrict__ out, int n4) {
    int i = blockIdx.x * 256 + threadIdx.x;
    if (i < n4) out[i] = make_float4(0.f, 0.f, 0.f, 0.f);
}
__global__ void scatter_out_kernel(const float4* __restrict__ h,
                                   const int* __restrict__ pos,
                                   float4* __restrict__ out) {
    int idx = blockIdx.x * 256 + threadIdx.x;
    if (idx < N_XROWS * 64) {
        int i = idx >> 6;
        int t = idx & 63;
        out[(size_t)__ldg(&pos[i]) * 64 + t] = h[(size_t)i * 64 + t];
    }
}

// ---------------- launch ----------------
extern "C" void kernel_launch(void* const* d_in, const int* in_sizes, int n_in,
                              void* d_out, int out_size) {
    const float* x     = (const float*)d_in[0];
    const float* motif = (const float*)d_in[1];
    const int*   rows  = (const int*)d_in[2];
    const int*   cols  = (const int*)d_in[3];
    const float* vals  = (const float*)d_in[4];
    const int*   pos   = (const int*)d_in[5];
    int wi = 6;
    if (n_in >= 13 && in_sizes[6] == 1) wi = 7;
    const float* w1 = (const float*)d_in[wi + 0];
    const float* b1 = (const float*)d_in[wi + 1];
    const float* w2 = (const float*)d_in[wi + 2];
    const float* b2 = (const float*)d_in[wi + 3];
    const float* w3 = (const float*)d_in[wi + 4];
    const float* b3 = (const float*)d_in[wi + 5];

    __half* support;
    float*  h1;
    __nv_bfloat16 *a2, *bt2;
    cudaGetSymbolAddress((void**)&support, g_support);
    cudaGetSymbolAddress((void**)&h1, g_h1);
    cudaGetSymbolAddress((void**)&a2, g_a2);
    cudaGetSymbolAddress((void**)&bt2, g_b2);

    cudaFuncSetAttribute(hmma_gemm_kernel,
                         cudaFuncAttributeMaxDynamicSharedMemorySize, GEMM_SMEM);

    // --- CSR build ---
    zero_cnt_kernel<<<(N_TOT + 255) / 256, 256>>>();
    hist_kernel<<<E_TOT / 256, 256>>>(rows);
    scan_kernel<<<1, 1024>>>();
    scatter_edges_kernel<<<E_TOT / 256, 256>>>(rows, cols, vals);

    const dim3 gemm_grid(M_PAD / 128, 2);   // 469 x 2

    // --- layer 1 (K=512) ---
    convertA_kernel<<<(N_TOT * 128) / 256, 256>>>(x, motif, a2);
    convertB_kernel<<<512, 256>>>(w1, 512, bt2);
    hmma_gemm_kernel<<<gemm_grid, 256, GEMM_SMEM>>>(a2, bt2, support, 512, N_TOT);
    spmm_bf16_kernel<<<N_TOT, 64>>>((const uint2*)support, (const float4*)b1, a2);

    // --- layer 2 (K=256) ---
    convertB_kernel<<<256, 256>>>(w2, 256, bt2);
    hmma_gemm_kernel<<<gemm_grid, 256, GEMM_SMEM>>>(a2, bt2, support, 256, N_TOT);
    spmm_bf16_kernel<<<N_TOT, 64>>>((const uint2*)support, (const float4*)b2, a2);

    // --- layer 3 (K=256) ---
    convertB_kernel<<<256, 256>>>(w3, 256, bt2);
    hmma_gemm_kernel<<<gemm_grid, 256, GEMM_SMEM>>>(a2, bt2, support, 256, N_TOT);
    spmm_f32_kernel<<<N_TOT, 64>>>((const uint2*)support, (const float4*)b3,
                                   (float4*)h1);

    // --- output ---
    int n4 = out_size / 4;
    zero_out_kernel<<<(n4 + 255) / 256, 256>>>((float4*)d_out, n4);
    scatter_out_kernel<<<(N_XROWS * 64 + 255) / 256, 256>>>(
        (const float4*)h1, pos, (float4*)d_out);
}

// round 5
// speedup vs baseline: 1.5620x; 1.2600x over previous
#include <cuda_runtime.h>
#include <cuda_fp16.h>
#include <cstdint>

#define N_XROWS   50000
#define N_MOTIF   10000
#define N_TOT     60000
#define E_TOT     1920000
#define NHID      256
#define PAD_N     65536
#define M_PAD     60032          // 469 * 128

// ---------------- device scratch (no allocs allowed) ----------------
__device__ int   g_cnt[N_TOT];
__device__ int   g_cur[N_TOT];
__device__ int   g_rowptr[N_TOT + 1];
__device__ int2  g_edges[E_TOT];
__device__ __half g_support[(size_t)N_TOT * NHID];     // fp16 support
__device__ float g_h1[(size_t)N_TOT * NHID];
__device__ __half g_a2[(size_t)M_PAD * 1024];          // A operand, hi|lo fp16 split
__device__ __half g_b1[256 * 512];                     // B^T operand, fp16, K-major

// ================= helpers =================
__device__ __forceinline__ uint32_t smem_u32(const void* p) {
    uint32_t a;
    asm("{ .reg .u64 t; cvta.to.shared.u64 t, %1; cvt.u32.u64 %0, t; }"
        : "=r"(a) : "l"(p));
    return a;
}
__device__ __forceinline__ void cp_async16(uint32_t dst, const void* src) {
    asm volatile("cp.async.cg.shared.global [%0], [%1], 16;"
                 :: "r"(dst), "l"(__cvta_generic_to_global(src)) : "memory");
}
#define CP_COMMIT() asm volatile("cp.async.commit_group;" ::: "memory")
#define CP_WAIT(n)  asm volatile("cp.async.wait_group %0;" :: "n"(n) : "memory")

__device__ __forceinline__ void mma16816(float* d, const uint32_t* a,
                                         const uint32_t* b) {
    asm volatile(
        "mma.sync.aligned.m16n8k16.row.col.f32.f16.f16.f32 "
        "{%0,%1,%2,%3}, {%4,%5,%6,%7}, {%8,%9}, {%0,%1,%2,%3};"
        : "+f"(d[0]), "+f"(d[1]), "+f"(d[2]), "+f"(d[3])
        : "r"(a[0]), "r"(a[1]), "r"(a[2]), "r"(a[3]), "r"(b[0]), "r"(b[1]));
}

__device__ __forceinline__ uint64_t pack4h(__half a, __half b, __half c, __half d) {
    __half2 p0 = __halves2half2(a, b);
    __half2 p1 = __halves2half2(c, d);
    uint32_t u0 = *(uint32_t*)&p0;
    uint32_t u1 = *(uint32_t*)&p1;
    return (uint64_t)u0 | ((uint64_t)u1 << 32);
}

// ---------------- CSR build ----------------
__global__ void zero_cnt_kernel() {
    int i = blockIdx.x * 256 + threadIdx.x;
    if (i < N_TOT) { g_cnt[i] = 0; g_cur[i] = 0; }
}
__global__ void hist_kernel(const int* __restrict__ rows) {
    int i = blockIdx.x * 256 + threadIdx.x;
    if (i < E_TOT) atomicAdd(&g_cnt[rows[i]], 1);
}
__global__ void scan_kernel() {
    __shared__ int wsum[32];
    __shared__ int chunk_total;
    __shared__ int s_running;
    const int tid = threadIdx.x;
    const int lane = tid & 31, wid = tid >> 5;
    if (tid == 0) s_running = 0;
    __syncthreads();
    for (int base = 0; base < N_TOT; base += 1024) {
        int i = base + tid;
        int x = (i < N_TOT) ? g_cnt[i] : 0;
        int v = x;
        #pragma unroll
        for (int off = 1; off < 32; off <<= 1) {
            int u = __shfl_up_sync(0xffffffffu, v, off);
            if (lane >= off) v += u;
        }
        if (lane == 31) wsum[wid] = v;
        __syncthreads();
        if (wid == 0) {
            int w = wsum[lane];
            #pragma unroll
            for (int off = 1; off < 32; off <<= 1) {
                int u = __shfl_up_sync(0xffffffffu, w, off);
                if (lane >= off) w += u;
            }
            wsum[lane] = w;
            if (lane == 31) chunk_total = w;
        }
        __syncthreads();
        int warp_prefix = (wid == 0) ? 0 : wsum[wid - 1];
        int excl = s_running + warp_prefix + v - x;
        if (i < N_TOT) g_rowptr[i] = excl;
        __syncthreads();
        if (tid == 0) s_running += chunk_total;
        __syncthreads();
    }
    if (tid == 0) g_rowptr[N_TOT] = s_running;
}
__global__ void scatter_edges_kernel(const int* __restrict__ rows,
                                     const int* __restrict__ cols,
                                     const float* __restrict__ vals) {
    int i = blockIdx.x * 256 + threadIdx.x;
    if (i < E_TOT) {
        int r = rows[i];
        int pos = g_rowptr[r] + atomicAdd(&g_cur[r], 1);
        g_edges[pos] = make_int2(cols[i], __float_as_int(vals[i]));
    }
}

// ---------------- fp16 split conversions ----------------
// x/motif [60000,512] fp32 -> g_a2 [m][0..511]=hi, [512..1023]=lo
__global__ void convertA_kernel(const float* __restrict__ x,
                                const float* __restrict__ motif,
                                __half* __restrict__ out) {
    int idx = blockIdx.x * 256 + threadIdx.x;      // N_TOT*128 threads
    if (idx >= N_TOT * 128) return;
    int m  = idx >> 7;
    int kq = (idx & 127) << 2;
    const float* src = (m < N_XROWS)
        ? x + (size_t)m * 512 + kq
        : motif + (size_t)(m - N_XROWS) * 512 + kq;
    float4 v = *(const float4*)src;
    __half h0 = __float2half_rn(v.x), h1 = __float2half_rn(v.y);
    __half h2 = __float2half_rn(v.z), h3 = __float2half_rn(v.w);
    __half l0 = __float2half_rn(v.x - __half2float(h0));
    __half l1 = __float2half_rn(v.y - __half2float(h1));
    __half l2 = __float2half_rn(v.z - __half2float(h2));
    __half l3 = __float2half_rn(v.w - __half2float(h3));
    size_t base = (size_t)m * 1024 + kq;
    *(uint64_t*)(out + base)       = pack4h(h0, h1, h2, h3);
    *(uint64_t*)(out + base + 512) = pack4h(l0, l1, l2, l3);
}

// B [K,N=256] fp32 -> g_b1 [n][k] fp16 (B^T, K-major, stride K)
__global__ void convertB_kernel(const float* __restrict__ B, int K,
                                __half* __restrict__ out) {
    int idx = blockIdx.x * 256 + threadIdx.x;    // K*256 threads
    if (idx >= K * 256) return;
    int k = idx >> 8;
    int n = idx & 255;
    out[(size_t)n * K + k] = __float2half_rn(B[idx]);
}

// ---------------- HMMA GEMM: C[M,256] = (A_hi + A_lo) @ B16^T ----
// CTA tile 128x128, BK=32, 8 warps (4 along M, 2 along N), 3-stage cp.async.
// 2 passes over K: A_hi then A_lo, same fp16 B. Epilogue writes fp16.
#define SA 40                          // padded SMEM row stride (elements)
#define STAGE_ELEMS (2 * 128 * SA)     // A tile + B tile
#define GEMM_SMEM   (3 * STAGE_ELEMS * 2)

__global__ void __launch_bounds__(256, 1)
hmma_gemm_kernel(const __half* __restrict__ A2,
                 const __half* __restrict__ B1,
                 __half* __restrict__ C, int K, int M) {
    extern __shared__ __half sm[];
    const int t    = threadIdx.x;
    const int lane = t & 31, wid = t >> 5;
    const int wm   = wid & 3, wn = wid >> 2;
    const int gid  = lane >> 2, tid4 = lane & 3;
    const int row0 = blockIdx.x * 128;
    const int col0 = blockIdx.y * 128;
    const int strideA = 2 * K;
    const int KB = K >> 5;            // 32-wide chunks per pass
    const int CC = 2 * KB;            // A_hi pass + A_lo pass

    float acc[2][8][4];
    #pragma unroll
    for (int mi = 0; mi < 2; mi++)
        #pragma unroll
        for (int ni = 0; ni < 8; ni++)
            #pragma unroll
            for (int q = 0; q < 4; q++) acc[mi][ni][q] = 0.f;

    auto offs = [&](int c, int& aoff, int& boff) {
        int pass = (c >= KB) ? 1 : 0;
        int kb = c - pass * KB;
        aoff = pass * K + (kb << 5);
        boff = (kb << 5);
    };
    auto load_chunk = [&](int stage, int aoff, int boff) {
        __half* s  = sm + stage * STAGE_ELEMS;
        __half* sB = s + 128 * SA;
        #pragma unroll
        for (int j = 0; j < 2; j++) {
            int u = j * 256 + t;
            int r = u >> 2, q = u & 3;
            cp_async16(smem_u32(s + r * SA + q * 8),
                       A2 + (size_t)(row0 + r) * strideA + aoff + q * 8);
        }
        #pragma unroll
        for (int j = 0; j < 2; j++) {
            int u = j * 256 + t;
            int r = u >> 2, q = u & 3;
            cp_async16(smem_u32(sB + r * SA + q * 8),
                       B1 + (size_t)(col0 + r) * K + boff + q * 8);
        }
        CP_COMMIT();
    };

    {
        int a0, b0, a1, b1;
        offs(0, a0, b0); load_chunk(0, a0, b0);
        offs(1, a1, b1); load_chunk(1, a1, b1);
    }

    for (int c = 0; c < CC; c++) {
        if (c < CC - 1) CP_WAIT(1); else CP_WAIT(0);
        __syncthreads();
        if (c + 2 < CC) {
            int ao, bo;
            offs(c + 2, ao, bo);
            load_chunk((c + 2) % 3, ao, bo);
        }
        const __half* s  = sm + (c % 3) * STAGE_ELEMS;
        const __half* sB = s + 128 * SA;
        #pragma unroll
        for (int ks = 0; ks < 2; ks++) {
            uint32_t a[2][4], b[8][2];
            #pragma unroll
            for (int mi = 0; mi < 2; mi++) {
                int r0 = wm * 32 + mi * 16 + gid;
                int kc = ks * 16 + tid4 * 2;
                a[mi][0] = *(const uint32_t*)(s + (size_t)r0 * SA + kc);
                a[mi][1] = *(const uint32_t*)(s + (size_t)(r0 + 8) * SA + kc);
                a[mi][2] = *(const uint32_t*)(s + (size_t)r0 * SA + kc + 8);
                a[mi][3] = *(const uint32_t*)(s + (size_t)(r0 + 8) * SA + kc + 8);
            }
            #pragma unroll
            for (int ni = 0; ni < 8; ni++) {
                int n0 = wn * 64 + ni * 8 + gid;
                int kc = ks * 16 + tid4 * 2;
                b[ni][0] = *(const uint32_t*)(sB + (size_t)n0 * SA + kc);
                b[ni][1] = *(const uint32_t*)(sB + (size_t)n0 * SA + kc + 8);
            }
            #pragma unroll
            for (int mi = 0; mi < 2; mi++)
                #pragma unroll
                for (int ni = 0; ni < 8; ni++)
                    mma16816(acc[mi][ni], a[mi], b[ni]);
        }
    }

    // epilogue -> fp16
    #pragma unroll
    for (int mi = 0; mi < 2; mi++) {
        int r = row0 + wm * 32 + mi * 16 + gid;
        #pragma unroll
        for (int ni = 0; ni < 8; ni++) {
            int cidx = col0 + wn * 64 + ni * 8 + tid4 * 2;
            if (r < M)
                *(__half2*)(C + (size_t)r * 256 + cidx) =
                    __floats2half2_rn(acc[mi][ni][0], acc[mi][ni][1]);
            if (r + 8 < M)
                *(__half2*)(C + (size_t)(r + 8) * 256 + cidx) =
                    __floats2half2_rn(acc[mi][ni][2], acc[mi][ni][3]);
        }
    }
}

// ---------------- SpMM: relu(bias + sum val*support_fp16[col]) ----------
// 64 threads/row; thread t covers cols [4t, 4t+4). Edge loop unrolled x4
// with independent gathers (MLP=4) and 2 accumulators.
__device__ __forceinline__ void fma4(float4& acc, float v, uint2 raw) {
    float2 f0 = __half22float2(*(__half2*)&raw.x);
    float2 f1 = __half22float2(*(__half2*)&raw.y);
    acc.x = fmaf(v, f0.x, acc.x);
    acc.y = fmaf(v, f0.y, acc.y);
    acc.z = fmaf(v, f1.x, acc.z);
    acc.w = fmaf(v, f1.y, acc.w);
}

__device__ __forceinline__ float4 spmm_row(const uint2* __restrict__ sup2,
                                           int row, int t) {
    int s = g_rowptr[row];
    int e = g_rowptr[row + 1];
    float4 acc0 = make_float4(0.f, 0.f, 0.f, 0.f);
    float4 acc1 = make_float4(0.f, 0.f, 0.f, 0.f);
    int i = s;
    for (; i + 4 <= e; i += 4) {
        int2 e0 = __ldg(&g_edges[i]);
        int2 e1 = __ldg(&g_edges[i + 1]);
        int2 e2 = __ldg(&g_edges[i + 2]);
        int2 e3 = __ldg(&g_edges[i + 3]);
        uint2 r0 = __ldg(&sup2[(size_t)e0.x * 64 + t]);
        uint2 r1 = __ldg(&sup2[(size_t)e1.x * 64 + t]);
        uint2 r2 = __ldg(&sup2[(size_t)e2.x * 64 + t]);
        uint2 r3 = __ldg(&sup2[(size_t)e3.x * 64 + t]);
        fma4(acc0, __int_as_float(e0.y), r0);
        fma4(acc1, __int_as_float(e1.y), r1);
        fma4(acc0, __int_as_float(e2.y), r2);
        fma4(acc1, __int_as_float(e3.y), r3);
    }
    for (; i < e; i++) {
        int2 ed = __ldg(&g_edges[i]);
        uint2 r0 = __ldg(&sup2[(size_t)ed.x * 64 + t]);
        fma4(acc0, __int_as_float(ed.y), r0);
    }
    acc0.x += acc1.x; acc0.y += acc1.y; acc0.z += acc1.z; acc0.w += acc1.w;
    return acc0;
}

__global__ void __launch_bounds__(64)
spmm_h16_kernel(const uint2* __restrict__ sup2,
                const float4* __restrict__ bias,
                __half* __restrict__ a2) {
    const int row = blockIdx.x;
    const int t   = threadIdx.x;
    float4 acc = spmm_row(sup2, row, t);
    float4 b = __ldg(&bias[t]);
    float ox = fmaxf(acc.x + b.x, 0.f);
    float oy = fmaxf(acc.y + b.y, 0.f);
    float oz = fmaxf(acc.z + b.z, 0.f);
    float ow = fmaxf(acc.w + b.w, 0.f);
    __half h0 = __float2half_rn(ox), h1 = __float2half_rn(oy);
    __half h2 = __float2half_rn(oz), h3 = __float2half_rn(ow);
    __half l0 = __float2half_rn(ox - __half2float(h0));
    __half l1 = __float2half_rn(oy - __half2float(h1));
    __half l2 = __float2half_rn(oz - __half2float(h2));
    __half l3 = __float2half_rn(ow - __half2float(h3));
    size_t base = (size_t)row * 512 + t * 4;
    *(uint64_t*)(a2 + base)       = pack4h(h0, h1, h2, h3);
    *(uint64_t*)(a2 + base + 256) = pack4h(l0, l1, l2, l3);
}

__global__ void __launch_bounds__(64)
spmm_f32_kernel(const uint2* __restrict__ sup2,
                const float4* __restrict__ bias,
                float4* __restrict__ out) {
    const int row = blockIdx.x;
    const int t   = threadIdx.x;
    float4 acc = spmm_row(sup2, row, t);
    float4 b = __ldg(&bias[t]);
    float4 o;
    o.x = fmaxf(acc.x + b.x, 0.f);
    o.y = fmaxf(acc.y + b.y, 0.f);
    o.z = fmaxf(acc.z + b.z, 0.f);
    o.w = fmaxf(acc.w + b.w, 0.f);
    out[(size_t)row * 64 + t] = o;
}

// ---------------- output: zero + row scatter ----------------
__global__ void zero_out_kernel(float4* __restrict__ out, int n4) {
    int i = blockIdx.x * 256 + threadIdx.x;
    if (i < n4) out[i] = make_float4(0.f, 0.f, 0.f, 0.f);
}
__global__ void scatter_out_kernel(const float4* __restrict__ h,
                                   const int* __restrict__ pos,
                                   float4* __restrict__ out) {
    int idx = blockIdx.x * 256 + threadIdx.x;
    if (idx < N_XROWS * 64) {
        int i = idx >> 6;
        int t = idx & 63;
        out[(size_t)__ldg(&pos[i]) * 64 + t] = h[(size_t)i * 64 + t];
    }
}

// ---------------- launch ----------------
extern "C" void kernel_launch(void* const* d_in, const int* in_sizes, int n_in,
                              void* d_out, int out_size) {
    const float* x     = (const float*)d_in[0];
    const float* motif = (const float*)d_in[1];
    const int*   rows  = (const int*)d_in[2];
    const int*   cols  = (const int*)d_in[3];
    const float* vals  = (const float*)d_in[4];
    const int*   pos   = (const int*)d_in[5];
    int wi = 6;
    if (n_in >= 13 && in_sizes[6] == 1) wi = 7;
    const float* w1 = (const float*)d_in[wi + 0];
    const float* b1 = (const float*)d_in[wi + 1];
    const float* w2 = (const float*)d_in[wi + 2];
    const float* b2 = (const float*)d_in[wi + 3];
    const float* w3 = (const float*)d_in[wi + 4];
    const float* b3 = (const float*)d_in[wi + 5];

    __half* support;
    float*  h1;
    __half *a2, *bt1;
    cudaGetSymbolAddress((void**)&support, g_support);
    cudaGetSymbolAddress((void**)&h1, g_h1);
    cudaGetSymbolAddress((void**)&a2, g_a2);
    cudaGetSymbolAddress((void**)&bt1, g_b1);

    cudaFuncSetAttribute(hmma_gemm_kernel,
                         cudaFuncAttributeMaxDynamicSharedMemorySize, GEMM_SMEM);

    // --- CSR build ---
    zero_cnt_kernel<<<(N_TOT + 255) / 256, 256>>>();
    hist_kernel<<<E_TOT / 256, 256>>>(rows);
    scan_kernel<<<1, 1024>>>();
    scatter_edges_kernel<<<E_TOT / 256, 256>>>(rows, cols, vals);

    const dim3 gemm_grid(M_PAD / 128, 2);   // 469 x 2

    // --- layer 1 (K=512) ---
    convertA_kernel<<<(N_TOT * 128) / 256, 256>>>(x, motif, a2);
    convertB_kernel<<<512, 256>>>(w1, 512, bt1);
    hmma_gemm_kernel<<<gemm_grid, 256, GEMM_SMEM>>>(a2, bt1, support, 512, N_TOT);
    spmm_h16_kernel<<<N_TOT, 64>>>((const uint2*)support, (const float4*)b1, a2);

    // --- layer 2 (K=256) ---
    convertB_kernel<<<256, 256>>>(w2, 256, bt1);
    hmma_gemm_kernel<<<gemm_grid, 256, GEMM_SMEM>>>(a2, bt1, support, 256, N_TOT);
    spmm_h16_kernel<<<N_TOT, 64>>>((const uint2*)support, (const float4*)b2, a2);

    // --- layer 3 (K=256) ---
    convertB_kernel<<<256, 256>>>(w3, 256, bt1);
    hmma_gemm_kernel<<<gemm_grid, 256, GEMM_SMEM>>>(a2, bt1, support, 256, N_TOT);
    spmm_f32_kernel<<<N_TOT, 64>>>((const uint2*)support, (const float4*)b3,
                                   (float4*)h1);

    // --- output ---
    int n4 = out_size / 4;
    zero_out_kernel<<<(n4 + 255) / 256, 256>>>((float4*)d_out, n4);
    scatter_out_kernel<<<(N_XROWS * 64 + 255) / 256, 256>>>(
        (const float4*)h1, pos, (float4*)d_out);
}

// round 6
// speedup vs baseline: 1.6631x; 1.0647x over previous
#include <cuda_runtime.h>
#include <cuda_fp16.h>
#include <cstdint>

#define N_XROWS   50000
#define N_MOTIF   10000
#define N_TOT     60000
#define E_TOT     1920000
#define NHID      256
#define PAD_N     65536
#define M_PAD     60032          // 469 * 128

// ---------------- device scratch (no allocs allowed) ----------------
__device__ int   g_cnt[N_TOT];
__device__ int   g_cur[N_TOT];
__device__ int   g_rowptr[N_TOT + 1];
__device__ int2  g_edges[E_TOT];
__device__ __half g_support[(size_t)N_TOT * NHID];     // fp16 support
__device__ __half g_a2[(size_t)M_PAD * 1024];          // A operand, hi|lo fp16 split
__device__ __half g_b1[256 * 512];                     // B^T operand, fp16, K-major

// ================= helpers =================
__device__ __forceinline__ uint32_t smem_u32(const void* p) {
    uint32_t a;
    asm("{ .reg .u64 t; cvta.to.shared.u64 t, %1; cvt.u32.u64 %0, t; }"
        : "=r"(a) : "l"(p));
    return a;
}
__device__ __forceinline__ void cp_async16(uint32_t dst, const void* src) {
    asm volatile("cp.async.cg.shared.global [%0], [%1], 16;"
                 :: "r"(dst), "l"(__cvta_generic_to_global(src)) : "memory");
}
#define CP_COMMIT() asm volatile("cp.async.commit_group;" ::: "memory")
#define CP_WAIT(n)  asm volatile("cp.async.wait_group %0;" :: "n"(n) : "memory")

__device__ __forceinline__ void mma16816(float* d, const uint32_t* a,
                                         const uint32_t* b) {
    asm volatile(
        "mma.sync.aligned.m16n8k16.row.col.f32.f16.f16.f32 "
        "{%0,%1,%2,%3}, {%4,%5,%6,%7}, {%8,%9}, {%0,%1,%2,%3};"
        : "+f"(d[0]), "+f"(d[1]), "+f"(d[2]), "+f"(d[3])
        : "r"(a[0]), "r"(a[1]), "r"(a[2]), "r"(a[3]), "r"(b[0]), "r"(b[1]));
}

__device__ __forceinline__ uint64_t pack4h(__half a, __half b, __half c, __half d) {
    __half2 p0 = __halves2half2(a, b);
    __half2 p1 = __halves2half2(c, d);
    uint32_t u0 = *(uint32_t*)&p0;
    uint32_t u1 = *(uint32_t*)&p1;
    return (uint64_t)u0 | ((uint64_t)u1 << 32);
}

// ---------------- CSR build ----------------
__global__ void zero_cnt_kernel() {
    int i = blockIdx.x * 256 + threadIdx.x;
    if (i < N_TOT) { g_cnt[i] = 0; g_cur[i] = 0; }
}
__global__ void hist_kernel(const int* __restrict__ rows) {
    int i = blockIdx.x * 256 + threadIdx.x;
    if (i < E_TOT) atomicAdd(&g_cnt[rows[i]], 1);
}
__global__ void scan_kernel() {
    __shared__ int wsum[32];
    __shared__ int chunk_total;
    __shared__ int s_running;
    const int tid = threadIdx.x;
    const int lane = tid & 31, wid = tid >> 5;
    if (tid == 0) s_running = 0;
    __syncthreads();
    for (int base = 0; base < N_TOT; base += 1024) {
        int i = base + tid;
        int x = (i < N_TOT) ? g_cnt[i] : 0;
        int v = x;
        #pragma unroll
        for (int off = 1; off < 32; off <<= 1) {
            int u = __shfl_up_sync(0xffffffffu, v, off);
            if (lane >= off) v += u;
        }
        if (lane == 31) wsum[wid] = v;
        __syncthreads();
        if (wid == 0) {
            int w = wsum[lane];
            #pragma unroll
            for (int off = 1; off < 32; off <<= 1) {
                int u = __shfl_up_sync(0xffffffffu, w, off);
                if (lane >= off) w += u;
            }
            wsum[lane] = w;
            if (lane == 31) chunk_total = w;
        }
        __syncthreads();
        int warp_prefix = (wid == 0) ? 0 : wsum[wid - 1];
        int excl = s_running + warp_prefix + v - x;
        if (i < N_TOT) g_rowptr[i] = excl;
        __syncthreads();
        if (tid == 0) s_running += chunk_total;
        __syncthreads();
    }
    if (tid == 0) g_rowptr[N_TOT] = s_running;
}
__global__ void scatter_edges_kernel(const int* __restrict__ rows,
                                     const int* __restrict__ cols,
                                     const float* __restrict__ vals) {
    int i = blockIdx.x * 256 + threadIdx.x;
    if (i < E_TOT) {
        int r = rows[i];
        int pos = g_rowptr[r] + atomicAdd(&g_cur[r], 1);
        g_edges[pos] = make_int2(cols[i], __float_as_int(vals[i]));
    }
}

// ---------------- fp16 split conversions ----------------
// x/motif [60000,512] fp32 -> g_a2 [m][0..511]=hi, [512..1023]=lo
__global__ void convertA_kernel(const float* __restrict__ x,
                                const float* __restrict__ motif,
                                __half* __restrict__ out) {
    int idx = blockIdx.x * 256 + threadIdx.x;      // N_TOT*128 threads
    if (idx >= N_TOT * 128) return;
    int m  = idx >> 7;
    int kq = (idx & 127) << 2;
    const float* src = (m < N_XROWS)
        ? x + (size_t)m * 512 + kq
        : motif + (size_t)(m - N_XROWS) * 512 + kq;
    float4 v = *(const float4*)src;
    __half h0 = __float2half_rn(v.x), h1 = __float2half_rn(v.y);
    __half h2 = __float2half_rn(v.z), h3 = __float2half_rn(v.w);
    __half l0 = __float2half_rn(v.x - __half2float(h0));
    __half l1 = __float2half_rn(v.y - __half2float(h1));
    __half l2 = __float2half_rn(v.z - __half2float(h2));
    __half l3 = __float2half_rn(v.w - __half2float(h3));
    size_t base = (size_t)m * 1024 + kq;
    *(uint64_t*)(out + base)       = pack4h(h0, h1, h2, h3);
    *(uint64_t*)(out + base + 512) = pack4h(l0, l1, l2, l3);
}

// B [K,N=256] fp32 -> g_b1 [n][k] fp16 (B^T, K-major, stride K)
__global__ void convertB_kernel(const float* __restrict__ B, int K,
                                __half* __restrict__ out) {
    int idx = blockIdx.x * 256 + threadIdx.x;    // K*256 threads
    if (idx >= K * 256) return;
    int k = idx >> 8;
    int n = idx & 255;
    out[(size_t)n * K + k] = __float2half_rn(B[idx]);
}

// ---------------- HMMA GEMM: C[M,256] = (A_hi + A_lo) @ B16^T ----
// CTA tile 128x256 (full N), BK=32, 8 warps as 2(M) x 4(N), warp tile 64x64.
// 3-stage cp.async pipeline, 2 passes over K (A_hi, A_lo), fp16 epilogue.
#define SA 40                               // padded SMEM row stride (halfs)
#define STAGE_ELEMS ((128 + 256) * SA)      // A tile + B tile
#define GEMM_SMEM   (3 * STAGE_ELEMS * 2)   // 92160 bytes

__global__ void __launch_bounds__(256, 1)
hmma_gemm_kernel(const __half* __restrict__ A2,
                 const __half* __restrict__ B1,
                 __half* __restrict__ C, int K, int M) {
    extern __shared__ __half sm[];
    const int t    = threadIdx.x;
    const int lane = t & 31, wid = t >> 5;
    const int wm   = wid & 1, wn = wid >> 1;   // 2 x 4 warp grid
    const int gid  = lane >> 2, tid4 = lane & 3;
    const int row0 = blockIdx.x * 128;
    const int strideA = 2 * K;
    const int KB = K >> 5;            // 32-wide chunks per pass
    const int CC = 2 * KB;            // A_hi pass + A_lo pass

    float acc[4][8][4];
    #pragma unroll
    for (int mi = 0; mi < 4; mi++)
        #pragma unroll
        for (int ni = 0; ni < 8; ni++)
            #pragma unroll
            for (int q = 0; q < 4; q++) acc[mi][ni][q] = 0.f;

    auto offs = [&](int c, int& aoff, int& boff) {
        int pass = (c >= KB) ? 1 : 0;
        int kb = c - pass * KB;
        aoff = pass * K + (kb << 5);
        boff = (kb << 5);
    };
    auto load_chunk = [&](int stage, int aoff, int boff) {
        __half* s  = sm + stage * STAGE_ELEMS;
        __half* sB = s + 128 * SA;
        #pragma unroll
        for (int j = 0; j < 2; j++) {          // A: 128 rows x 32 halfs
            int u = j * 256 + t;
            int r = u >> 2, q = u & 3;
            cp_async16(smem_u32(s + r * SA + q * 8),
                       A2 + (size_t)(row0 + r) * strideA + aoff + q * 8);
        }
        #pragma unroll
        for (int j = 0; j < 4; j++) {          // B: 256 rows x 32 halfs
            int u = j * 256 + t;
            int r = u >> 2, q = u & 3;
            cp_async16(smem_u32(sB + r * SA + q * 8),
                       B1 + (size_t)r * K + boff + q * 8);
        }
        CP_COMMIT();
    };

    {
        int a0, b0, a1, b1;
        offs(0, a0, b0); load_chunk(0, a0, b0);
        offs(1, a1, b1); load_chunk(1, a1, b1);
    }

    for (int c = 0; c < CC; c++) {
        if (c < CC - 1) CP_WAIT(1); else CP_WAIT(0);
        __syncthreads();
        if (c + 2 < CC) {
            int ao, bo;
            offs(c + 2, ao, bo);
            load_chunk((c + 2) % 3, ao, bo);
        }
        const __half* s  = sm + (c % 3) * STAGE_ELEMS;
        const __half* sB = s + 128 * SA;
        #pragma unroll
        for (int ks = 0; ks < 2; ks++) {
            uint32_t a[4][4], b[8][2];
            const int kc = ks * 16 + tid4 * 2;
            #pragma unroll
            for (int mi = 0; mi < 4; mi++) {
                int r0 = wm * 64 + mi * 16 + gid;
                a[mi][0] = *(const uint32_t*)(s + (size_t)r0 * SA + kc);
                a[mi][1] = *(const uint32_t*)(s + (size_t)(r0 + 8) * SA + kc);
                a[mi][2] = *(const uint32_t*)(s + (size_t)r0 * SA + kc + 8);
                a[mi][3] = *(const uint32_t*)(s + (size_t)(r0 + 8) * SA + kc + 8);
            }
            #pragma unroll
            for (int ni = 0; ni < 8; ni++) {
                int n0 = wn * 64 + ni * 8 + gid;
                b[ni][0] = *(const uint32_t*)(sB + (size_t)n0 * SA + kc);
                b[ni][1] = *(const uint32_t*)(sB + (size_t)n0 * SA + kc + 8);
            }
            #pragma unroll
            for (int mi = 0; mi < 4; mi++)
                #pragma unroll
                for (int ni = 0; ni < 8; ni++)
                    mma16816(acc[mi][ni], a[mi], b[ni]);
        }
    }

    // epilogue -> fp16
    #pragma unroll
    for (int mi = 0; mi < 4; mi++) {
        int r = row0 + wm * 64 + mi * 16 + gid;
        #pragma unroll
        for (int ni = 0; ni < 8; ni++) {
            int cidx = wn * 64 + ni * 8 + tid4 * 2;
            if (r < M)
                *(__half2*)(C + (size_t)r * 256 + cidx) =
                    __floats2half2_rn(acc[mi][ni][0], acc[mi][ni][1]);
            if (r + 8 < M)
                *(__half2*)(C + (size_t)(r + 8) * 256 + cidx) =
                    __floats2half2_rn(acc[mi][ni][2], acc[mi][ni][3]);
        }
    }
}

// ---------------- SpMM: relu(bias + sum val*support_fp16[col]) ----------
// 64 threads/row; thread t covers cols [4t, 4t+4). Edge loop unrolled x4
// with independent gathers (MLP=4) and 2 accumulators.
__device__ __forceinline__ void fma4(float4& acc, float v, uint2 raw) {
    float2 f0 = __half22float2(*(__half2*)&raw.x);
    float2 f1 = __half22float2(*(__half2*)&raw.y);
    acc.x = fmaf(v, f0.x, acc.x);
    acc.y = fmaf(v, f0.y, acc.y);
    acc.z = fmaf(v, f1.x, acc.z);
    acc.w = fmaf(v, f1.y, acc.w);
}

__device__ __forceinline__ float4 spmm_row(const uint2* __restrict__ sup2,
                                           int row, int t) {
    int s = g_rowptr[row];
    int e = g_rowptr[row + 1];
    float4 acc0 = make_float4(0.f, 0.f, 0.f, 0.f);
    float4 acc1 = make_float4(0.f, 0.f, 0.f, 0.f);
    int i = s;
    for (; i + 4 <= e; i += 4) {
        int2 e0 = __ldg(&g_edges[i]);
        int2 e1 = __ldg(&g_edges[i + 1]);
        int2 e2 = __ldg(&g_edges[i + 2]);
        int2 e3 = __ldg(&g_edges[i + 3]);
        uint2 r0 = __ldg(&sup2[(size_t)e0.x * 64 + t]);
        uint2 r1 = __ldg(&sup2[(size_t)e1.x * 64 + t]);
        uint2 r2 = __ldg(&sup2[(size_t)e2.x * 64 + t]);
        uint2 r3 = __ldg(&sup2[(size_t)e3.x * 64 + t]);
        fma4(acc0, __int_as_float(e0.y), r0);
        fma4(acc1, __int_as_float(e1.y), r1);
        fma4(acc0, __int_as_float(e2.y), r2);
        fma4(acc1, __int_as_float(e3.y), r3);
    }
    for (; i < e; i++) {
        int2 ed = __ldg(&g_edges[i]);
        uint2 r0 = __ldg(&sup2[(size_t)ed.x * 64 + t]);
        fma4(acc0, __int_as_float(ed.y), r0);
    }
    acc0.x += acc1.x; acc0.y += acc1.y; acc0.z += acc1.z; acc0.w += acc1.w;
    return acc0;
}

__global__ void __launch_bounds__(64)
spmm_h16_kernel(const uint2* __restrict__ sup2,
                const float4* __restrict__ bias,
                __half* __restrict__ a2) {
    const int row = blockIdx.x;
    const int t   = threadIdx.x;
    float4 acc = spmm_row(sup2, row, t);
    float4 b = __ldg(&bias[t]);
    float ox = fmaxf(acc.x + b.x, 0.f);
    float oy = fmaxf(acc.y + b.y, 0.f);
    float oz = fmaxf(acc.z + b.z, 0.f);
    float ow = fmaxf(acc.w + b.w, 0.f);
    __half h0 = __float2half_rn(ox), h1 = __float2half_rn(oy);
    __half h2 = __float2half_rn(oz), h3 = __float2half_rn(ow);
    __half l0 = __float2half_rn(ox - __half2float(h0));
    __half l1 = __float2half_rn(oy - __half2float(h1));
    __half l2 = __float2half_rn(oz - __half2float(h2));
    __half l3 = __float2half_rn(ow - __half2float(h3));
    size_t base = (size_t)row * 512 + t * 4;
    *(uint64_t*)(a2 + base)       = pack4h(h0, h1, h2, h3);
    *(uint64_t*)(a2 + base + 256) = pack4h(l0, l1, l2, l3);
}

// Layer-3 SpMM fused with the output permutation: only rows < N_XROWS,
// writes relu(agg + b) directly at out[pos[row]].
__global__ void __launch_bounds__(64)
spmm_out_kernel(const uint2* __restrict__ sup2,
                const float4* __restrict__ bias,
                const int* __restrict__ pos,
                float4* __restrict__ out) {
    const int row = blockIdx.x;          // < N_XROWS
    const int t   = threadIdx.x;
    float4 acc = spmm_row(sup2, row, t);
    float4 b = __ldg(&bias[t]);
    float4 o;
    o.x = fmaxf(acc.x + b.x, 0.f);
    o.y = fmaxf(acc.y + b.y, 0.f);
    o.z = fmaxf(acc.z + b.z, 0.f);
    o.w = fmaxf(acc.w + b.w, 0.f);
    out[(size_t)__ldg(&pos[row]) * 64 + t] = o;
}

// ---------------- output zero ----------------
__global__ void zero_out_kernel(float4* __restrict__ out, int n4) {
    int i = blockIdx.x * 256 + threadIdx.x;
    if (i < n4) out[i] = make_float4(0.f, 0.f, 0.f, 0.f);
}

// ---------------- launch ----------------
extern "C" void kernel_launch(void* const* d_in, const int* in_sizes, int n_in,
                              void* d_out, int out_size) {
    const float* x     = (const float*)d_in[0];
    const float* motif = (const float*)d_in[1];
    const int*   rows  = (const int*)d_in[2];
    const int*   cols  = (const int*)d_in[3];
    const float* vals  = (const float*)d_in[4];
    const int*   pos   = (const int*)d_in[5];
    int wi = 6;
    if (n_in >= 13 && in_sizes[6] == 1) wi = 7;
    const float* w1 = (const float*)d_in[wi + 0];
    const float* b1 = (const float*)d_in[wi + 1];
    const float* w2 = (const float*)d_in[wi + 2];
    const float* b2 = (const float*)d_in[wi + 3];
    const float* w3 = (const float*)d_in[wi + 4];
    const float* b3 = (const float*)d_in[wi + 5];

    __half* support;
    __half *a2, *bt1;
    cudaGetSymbolAddress((void**)&support, g_support);
    cudaGetSymbolAddress((void**)&a2, g_a2);
    cudaGetSymbolAddress((void**)&bt1, g_b1);

    cudaFuncSetAttribute(hmma_gemm_kernel,
                         cudaFuncAttributeMaxDynamicSharedMemorySize, GEMM_SMEM);

    // --- CSR build ---
    zero_cnt_kernel<<<(N_TOT + 255) / 256, 256>>>();
    hist_kernel<<<E_TOT / 256, 256>>>(rows);
    scan_kernel<<<1, 1024>>>();
    scatter_edges_kernel<<<E_TOT / 256, 256>>>(rows, cols, vals);

    const int gemm_grid = M_PAD / 128;   // 469, full-N CTAs

    // --- layer 1 (K=512) ---
    convertA_kernel<<<(N_TOT * 128) / 256, 256>>>(x, motif, a2);
    convertB_kernel<<<512, 256>>>(w1, 512, bt1);
    hmma_gemm_kernel<<<gemm_grid, 256, GEMM_SMEM>>>(a2, bt1, support, 512, N_TOT);
    spmm_h16_kernel<<<N_TOT, 64>>>((const uint2*)support, (const float4*)b1, a2);

    // --- layer 2 (K=256) ---
    convertB_kernel<<<256, 256>>>(w2, 256, bt1);
    hmma_gemm_kernel<<<gemm_grid, 256, GEMM_SMEM>>>(a2, bt1, support, 256, N_TOT);
    spmm_h16_kernel<<<N_TOT, 64>>>((const uint2*)support, (const float4*)b2, a2);

    // --- layer 3 (K=256): SpMM fused with output scatter ---
    convertB_kernel<<<256, 256>>>(w3, 256, bt1);
    hmma_gemm_kernel<<<gemm_grid, 256, GEMM_SMEM>>>(a2, bt1, support, 256, N_TOT);

    int n4 = out_size / 4;
    zero_out_kernel<<<(n4 + 255) / 256, 256>>>((float4*)d_out, n4);
    spmm_out_kernel<<<N_XROWS, 64>>>((const uint2*)support, (const float4*)b3,
                                     pos, (float4*)d_out);
}

// round 7
// speedup vs baseline: 2.1511x; 1.2934x over previous
#include <cuda_runtime.h>
#include <cuda_fp16.h>
#include <cstdint>

#define N_XROWS   50000
#define N_MOTIF   10000
#define N_TOT     60000
#define E_TOT     1920000
#define NHID      256
#define PAD_N     65536
#define M_PAD     60032          // 469 * 128

// ---------------- device scratch (no allocs allowed) ----------------
__device__ int   g_cnt[N_TOT];
__device__ int   g_cur[N_TOT];
__device__ int   g_rowptr[N_TOT + 1];
__device__ int2  g_edges[E_TOT];
__device__ __half g_support[(size_t)N_TOT * NHID];     // fp16 support
__device__ __half g_a[(size_t)M_PAD * 512];            // A operand, fp16
__device__ __half g_b1[256 * 512];                     // B^T operand, fp16, K-major

// ================= helpers =================
__device__ __forceinline__ uint32_t smem_u32(const void* p) {
    uint32_t a;
    asm("{ .reg .u64 t; cvta.to.shared.u64 t, %1; cvt.u32.u64 %0, t; }"
        : "=r"(a) : "l"(p));
    return a;
}
__device__ __forceinline__ void cp_async16(uint32_t dst, const void* src) {
    asm volatile("cp.async.cg.shared.global [%0], [%1], 16;"
                 :: "r"(dst), "l"(__cvta_generic_to_global(src)) : "memory");
}
#define CP_COMMIT() asm volatile("cp.async.commit_group;" ::: "memory")
#define CP_WAIT(n)  asm volatile("cp.async.wait_group %0;" :: "n"(n) : "memory")

__device__ __forceinline__ void mma16816(float* d, const uint32_t* a,
                                         const uint32_t* b) {
    asm volatile(
        "mma.sync.aligned.m16n8k16.row.col.f32.f16.f16.f32 "
        "{%0,%1,%2,%3}, {%4,%5,%6,%7}, {%8,%9}, {%0,%1,%2,%3};"
        : "+f"(d[0]), "+f"(d[1]), "+f"(d[2]), "+f"(d[3])
        : "r"(a[0]), "r"(a[1]), "r"(a[2]), "r"(a[3]), "r"(b[0]), "r"(b[1]));
}

__device__ __forceinline__ uint64_t pack4h(__half a, __half b, __half c, __half d) {
    __half2 p0 = __halves2half2(a, b);
    __half2 p1 = __halves2half2(c, d);
    uint32_t u0 = *(uint32_t*)&p0;
    uint32_t u1 = *(uint32_t*)&p1;
    return (uint64_t)u0 | ((uint64_t)u1 << 32);
}

// ---------------- CSR build ----------------
__global__ void zero_cnt_kernel() {
    int i = blockIdx.x * 256 + threadIdx.x;
    if (i < N_TOT) { g_cnt[i] = 0; g_cur[i] = 0; }
}
__global__ void hist_kernel(const int* __restrict__ rows) {
    int i = blockIdx.x * 256 + threadIdx.x;
    if (i < E_TOT) atomicAdd(&g_cnt[rows[i]], 1);
}
__global__ void scan_kernel() {
    __shared__ int wsum[32];
    __shared__ int chunk_total;
    __shared__ int s_running;
    const int tid = threadIdx.x;
    const int lane = tid & 31, wid = tid >> 5;
    if (tid == 0) s_running = 0;
    __syncthreads();
    for (int base = 0; base < N_TOT; base += 1024) {
        int i = base + tid;
        int x = (i < N_TOT) ? g_cnt[i] : 0;
        int v = x;
        #pragma unroll
        for (int off = 1; off < 32; off <<= 1) {
            int u = __shfl_up_sync(0xffffffffu, v, off);
            if (lane >= off) v += u;
        }
        if (lane == 31) wsum[wid] = v;
        __syncthreads();
        if (wid == 0) {
            int w = wsum[lane];
            #pragma unroll
            for (int off = 1; off < 32; off <<= 1) {
                int u = __shfl_up_sync(0xffffffffu, w, off);
                if (lane >= off) w += u;
            }
            wsum[lane] = w;
            if (lane == 31) chunk_total = w;
        }
        __syncthreads();
        int warp_prefix = (wid == 0) ? 0 : wsum[wid - 1];
        int excl = s_running + warp_prefix + v - x;
        if (i < N_TOT) g_rowptr[i] = excl;
        __syncthreads();
        if (tid == 0) s_running += chunk_total;
        __syncthreads();
    }
    if (tid == 0) g_rowptr[N_TOT] = s_running;
}
__global__ void scatter_edges_kernel(const int* __restrict__ rows,
                                     const int* __restrict__ cols,
                                     const float* __restrict__ vals) {
    int i = blockIdx.x * 256 + threadIdx.x;
    if (i < E_TOT) {
        int r = rows[i];
        int pos = g_rowptr[r] + atomicAdd(&g_cur[r], 1);
        g_edges[pos] = make_int2(cols[i], __float_as_int(vals[i]));
    }
}

// ---------------- fp16 conversions ----------------
// x/motif [60000,512] fp32 -> g_a [m][0..511] fp16
__global__ void convertA_kernel(const float* __restrict__ x,
                                const float* __restrict__ motif,
                                __half* __restrict__ out) {
    int idx = blockIdx.x * 256 + threadIdx.x;      // N_TOT*128 threads
    if (idx >= N_TOT * 128) return;
    int m  = idx >> 7;
    int kq = (idx & 127) << 2;
    const float* src = (m < N_XROWS)
        ? x + (size_t)m * 512 + kq
        : motif + (size_t)(m - N_XROWS) * 512 + kq;
    float4 v = *(const float4*)src;
    *(uint64_t*)(out + (size_t)m * 512 + kq) =
        pack4h(__float2half_rn(v.x), __float2half_rn(v.y),
               __float2half_rn(v.z), __float2half_rn(v.w));
}

// B [K,N=256] fp32 -> g_b1 [n][k] fp16 (B^T, K-major, stride K)
__global__ void convertB_kernel(const float* __restrict__ B, int K,
                                __half* __restrict__ out) {
    int idx = blockIdx.x * 256 + threadIdx.x;    // K*256 threads
    if (idx >= K * 256) return;
    int k = idx >> 8;
    int n = idx & 255;
    out[(size_t)n * K + k] = __float2half_rn(B[idx]);
}

// ---------------- HMMA GEMM: C[M,256] = A16 @ B16^T (1 pass) ----
// CTA tile 128x256 (full N), BK=32, 8 warps as 2(M) x 4(N), warp tile 64x64.
// 3-stage cp.async pipeline, fp16 epilogue.
#define SA 40                               // padded SMEM row stride (halfs)
#define STAGE_ELEMS ((128 + 256) * SA)      // A tile + B tile
#define GEMM_SMEM   (3 * STAGE_ELEMS * 2)   // 92160 bytes

__global__ void __launch_bounds__(256, 1)
hmma_gemm_kernel(const __half* __restrict__ A,
                 const __half* __restrict__ B1,
                 __half* __restrict__ C, int K, int M) {
    extern __shared__ __half sm[];
    const int t    = threadIdx.x;
    const int lane = t & 31, wid = t >> 5;
    const int wm   = wid & 1, wn = wid >> 1;   // 2 x 4 warp grid
    const int gid  = lane >> 2, tid4 = lane & 3;
    const int row0 = blockIdx.x * 128;
    const int CC = K >> 5;            // 32-wide chunks, single pass

    float acc[4][8][4];
    #pragma unroll
    for (int mi = 0; mi < 4; mi++)
        #pragma unroll
        for (int ni = 0; ni < 8; ni++)
            #pragma unroll
            for (int q = 0; q < 4; q++) acc[mi][ni][q] = 0.f;

    auto load_chunk = [&](int stage, int koff) {
        __half* s  = sm + stage * STAGE_ELEMS;
        __half* sB = s + 128 * SA;
        #pragma unroll
        for (int j = 0; j < 2; j++) {          // A: 128 rows x 32 halfs
            int u = j * 256 + t;
            int r = u >> 2, q = u & 3;
            cp_async16(smem_u32(s + r * SA + q * 8),
                       A + (size_t)(row0 + r) * K + koff + q * 8);
        }
        #pragma unroll
        for (int j = 0; j < 4; j++) {          // B: 256 rows x 32 halfs
            int u = j * 256 + t;
            int r = u >> 2, q = u & 3;
            cp_async16(smem_u32(sB + r * SA + q * 8),
                       B1 + (size_t)r * K + koff + q * 8);
        }
        CP_COMMIT();
    };

    load_chunk(0, 0);
    load_chunk(1, 32);

    for (int c = 0; c < CC; c++) {
        if (c < CC - 1) CP_WAIT(1); else CP_WAIT(0);
        __syncthreads();
        if (c + 2 < CC) load_chunk((c + 2) % 3, (c + 2) << 5);
        const __half* s  = sm + (c % 3) * STAGE_ELEMS;
        const __half* sB = s + 128 * SA;
        #pragma unroll
        for (int ks = 0; ks < 2; ks++) {
            uint32_t a[4][4], b[8][2];
            const int kc = ks * 16 + tid4 * 2;
            #pragma unroll
            for (int mi = 0; mi < 4; mi++) {
                int r0 = wm * 64 + mi * 16 + gid;
                a[mi][0] = *(const uint32_t*)(s + (size_t)r0 * SA + kc);
                a[mi][1] = *(const uint32_t*)(s + (size_t)(r0 + 8) * SA + kc);
                a[mi][2] = *(const uint32_t*)(s + (size_t)r0 * SA + kc + 8);
                a[mi][3] = *(const uint32_t*)(s + (size_t)(r0 + 8) * SA + kc + 8);
            }
            #pragma unroll
            for (int ni = 0; ni < 8; ni++) {
                int n0 = wn * 64 + ni * 8 + gid;
                b[ni][0] = *(const uint32_t*)(sB + (size_t)n0 * SA + kc);
                b[ni][1] = *(const uint32_t*)(sB + (size_t)n0 * SA + kc + 8);
            }
            #pragma unroll
            for (int mi = 0; mi < 4; mi++)
                #pragma unroll
                for (int ni = 0; ni < 8; ni++)
                    mma16816(acc[mi][ni], a[mi], b[ni]);
        }
    }

    // epilogue -> fp16
    #pragma unroll
    for (int mi = 0; mi < 4; mi++) {
        int r = row0 + wm * 64 + mi * 16 + gid;
        #pragma unroll
        for (int ni = 0; ni < 8; ni++) {
            int cidx = wn * 64 + ni * 8 + tid4 * 2;
            if (r < M)
                *(__half2*)(C + (size_t)r * 256 + cidx) =
                    __floats2half2_rn(acc[mi][ni][0], acc[mi][ni][1]);
            if (r + 8 < M)
                *(__half2*)(C + (size_t)(r + 8) * 256 + cidx) =
                    __floats2half2_rn(acc[mi][ni][2], acc[mi][ni][3]);
        }
    }
}

// ---------------- SpMM: relu(bias + sum val*support_fp16[col]) ----------
// 64 threads/row; thread t covers cols [4t, 4t+4). Edge loop unrolled x4
// with independent gathers (MLP=4) and 2 accumulators.
__device__ __forceinline__ void fma4(float4& acc, float v, uint2 raw) {
    float2 f0 = __half22float2(*(__half2*)&raw.x);
    float2 f1 = __half22float2(*(__half2*)&raw.y);
    acc.x = fmaf(v, f0.x, acc.x);
    acc.y = fmaf(v, f0.y, acc.y);
    acc.z = fmaf(v, f1.x, acc.z);
    acc.w = fmaf(v, f1.y, acc.w);
}

__device__ __forceinline__ float4 spmm_row(const uint2* __restrict__ sup2,
                                           int row, int t) {
    int s = g_rowptr[row];
    int e = g_rowptr[row + 1];
    float4 acc0 = make_float4(0.f, 0.f, 0.f, 0.f);
    float4 acc1 = make_float4(0.f, 0.f, 0.f, 0.f);
    int i = s;
    for (; i + 4 <= e; i += 4) {
        int2 e0 = __ldg(&g_edges[i]);
        int2 e1 = __ldg(&g_edges[i + 1]);
        int2 e2 = __ldg(&g_edges[i + 2]);
        int2 e3 = __ldg(&g_edges[i + 3]);
        uint2 r0 = __ldg(&sup2[(size_t)e0.x * 64 + t]);
        uint2 r1 = __ldg(&sup2[(size_t)e1.x * 64 + t]);
        uint2 r2 = __ldg(&sup2[(size_t)e2.x * 64 + t]);
        uint2 r3 = __ldg(&sup2[(size_t)e3.x * 64 + t]);
        fma4(acc0, __int_as_float(e0.y), r0);
        fma4(acc1, __int_as_float(e1.y), r1);
        fma4(acc0, __int_as_float(e2.y), r2);
        fma4(acc1, __int_as_float(e3.y), r3);
    }
    for (; i < e; i++) {
        int2 ed = __ldg(&g_edges[i]);
        uint2 r0 = __ldg(&sup2[(size_t)ed.x * 64 + t]);
        fma4(acc0, __int_as_float(ed.y), r0);
    }
    acc0.x += acc1.x; acc0.y += acc1.y; acc0.z += acc1.z; acc0.w += acc1.w;
    return acc0;
}

// writes next layer's fp16 A operand (stride 256)
__global__ void __launch_bounds__(64)
spmm_h16_kernel(const uint2* __restrict__ sup2,
                const float4* __restrict__ bias,
                __half* __restrict__ a_next) {
    const int row = blockIdx.x;
    const int t   = threadIdx.x;
    float4 acc = spmm_row(sup2, row, t);
    float4 b = __ldg(&bias[t]);
    float ox = fmaxf(acc.x + b.x, 0.f);
    float oy = fmaxf(acc.y + b.y, 0.f);
    float oz = fmaxf(acc.z + b.z, 0.f);
    float ow = fmaxf(acc.w + b.w, 0.f);
    *(uint64_t*)(a_next + (size_t)row * 256 + t * 4) =
        pack4h(__float2half_rn(ox), __float2half_rn(oy),
               __float2half_rn(oz), __float2half_rn(ow));
}

// Layer-3 SpMM fused with the output permutation: only rows < N_XROWS,
// writes relu(agg + b) directly at out[pos[row]].
__global__ void __launch_bounds__(64)
spmm_out_kernel(const uint2* __restrict__ sup2,
                const float4* __restrict__ bias,
                const int* __restrict__ pos,
                float4* __restrict__ out) {
    const int row = blockIdx.x;          // < N_XROWS
    const int t   = threadIdx.x;
    float4 acc = spmm_row(sup2, row, t);
    float4 b = __ldg(&bias[t]);
    float4 o;
    o.x = fmaxf(acc.x + b.x, 0.f);
    o.y = fmaxf(acc.y + b.y, 0.f);
    o.z = fmaxf(acc.z + b.z, 0.f);
    o.w = fmaxf(acc.w + b.w, 0.f);
    out[(size_t)__ldg(&pos[row]) * 64 + t] = o;
}

// ---------------- output zero ----------------
__global__ void zero_out_kernel(float4* __restrict__ out, int n4) {
    int i = blockIdx.x * 256 + threadIdx.x;
    if (i < n4) out[i] = make_float4(0.f, 0.f, 0.f, 0.f);
}

// ---------------- launch ----------------
extern "C" void kernel_launch(void* const* d_in, const int* in_sizes, int n_in,
                              void* d_out, int out_size) {
    const float* x     = (const float*)d_in[0];
    const float* motif = (const float*)d_in[1];
    const int*   rows  = (const int*)d_in[2];
    const int*   cols  = (const int*)d_in[3];
    const float* vals  = (const float*)d_in[4];
    const int*   pos   = (const int*)d_in[5];
    int wi = 6;
    if (n_in >= 13 && in_sizes[6] == 1) wi = 7;
    const float* w1 = (const float*)d_in[wi + 0];
    const float* b1 = (const float*)d_in[wi + 1];
    const float* w2 = (const float*)d_in[wi + 2];
    const float* b2 = (const float*)d_in[wi + 3];
    const float* w3 = (const float*)d_in[wi + 4];
    const float* b3 = (const float*)d_in[wi + 5];

    __half* support;
    __half *a, *bt1;
    cudaGetSymbolAddress((void**)&support, g_support);
    cudaGetSymbolAddress((void**)&a, g_a);
    cudaGetSymbolAddress((void**)&bt1, g_b1);

    cudaFuncSetAttribute(hmma_gemm_kernel,
                         cudaFuncAttributeMaxDynamicSharedMemorySize, GEMM_SMEM);

    // --- CSR build ---
    zero_cnt_kernel<<<(N_TOT + 255) / 256, 256>>>();
    hist_kernel<<<E_TOT / 256, 256>>>(rows);
    scan_kernel<<<1, 1024>>>();
    scatter_edges_kernel<<<E_TOT / 256, 256>>>(rows, cols, vals);

    const int gemm_grid = M_PAD / 128;   // 469, full-N CTAs

    // --- layer 1 (K=512) ---
    convertA_kernel<<<(N_TOT * 128) / 256, 256>>>(x, motif, a);
    convertB_kernel<<<512, 256>>>(w1, 512, bt1);
    hmma_gemm_kernel<<<gemm_grid, 256, GEMM_SMEM>>>(a, bt1, support, 512, N_TOT);
    spmm_h16_kernel<<<N_TOT, 64>>>((const uint2*)support, (const float4*)b1, a);

    // --- layer 2 (K=256) ---
    convertB_kernel<<<256, 256>>>(w2, 256, bt1);
    hmma_gemm_kernel<<<gemm_grid, 256, GEMM_SMEM>>>(a, bt1, support, 256, N_TOT);
    spmm_h16_kernel<<<N_TOT, 64>>>((const uint2*)support, (const float4*)b2, a);

    // --- layer 3 (K=256): SpMM fused with output scatter ---
    convertB_kernel<<<256, 256>>>(w3, 256, bt1);
    hmma_gemm_kernel<<<gemm_grid, 256, GEMM_SMEM>>>(a, bt1, support, 256, N_TOT);

    int n4 = out_size / 4;
    zero_out_kernel<<<(n4 + 255) / 256, 256>>>((float4*)d_out, n4);
    spmm_out_kernel<<<N_XROWS, 64>>>((const uint2*)support, (const float4*)b3,
                                     pos, (float4*)d_out);
}

// round 8
// speedup vs baseline: 2.3959x; 1.1138x over previous
#include <cuda_runtime.h>
#include <cuda_fp16.h>
#include <cstdint>

#define N_XROWS   50000
#define N_MOTIF   10000
#define N_TOT     60000
#define E_TOT     1920000
#define NHID      256
#define PAD_N     65536
#define M_PAD     60032          // 469 * 128

// ---------------- device scratch (no allocs allowed) ----------------
__device__ int   g_cnt[N_TOT];
__device__ int   g_cur[N_TOT];
__device__ int   g_rowptr[N_TOT + 1];
__device__ int2  g_edges[E_TOT];
__device__ __half g_support[(size_t)N_TOT * NHID];     // fp16 support
__device__ __half g_a[(size_t)M_PAD * 512];            // A operand, fp16
__device__ __half g_b1[256 * 512];                     // B^T operand, fp16, K-major

// ================= helpers =================
__device__ __forceinline__ uint32_t smem_u32(const void* p) {
    uint32_t a;
    asm("{ .reg .u64 t; cvta.to.shared.u64 t, %1; cvt.u32.u64 %0, t; }"
        : "=r"(a) : "l"(p));
    return a;
}
__device__ __forceinline__ void cp_async16(uint32_t dst, const void* src) {
    asm volatile("cp.async.cg.shared.global [%0], [%1], 16;"
                 :: "r"(dst), "l"(__cvta_generic_to_global(src)) : "memory");
}
#define CP_COMMIT() asm volatile("cp.async.commit_group;" ::: "memory")
#define CP_WAIT(n)  asm volatile("cp.async.wait_group %0;" :: "n"(n) : "memory")

__device__ __forceinline__ void mma16816(float* d, const uint32_t* a,
                                         const uint32_t* b) {
    asm volatile(
        "mma.sync.aligned.m16n8k16.row.col.f32.f16.f16.f32 "
        "{%0,%1,%2,%3}, {%4,%5,%6,%7}, {%8,%9}, {%0,%1,%2,%3};"
        : "+f"(d[0]), "+f"(d[1]), "+f"(d[2]), "+f"(d[3])
        : "r"(a[0]), "r"(a[1]), "r"(a[2]), "r"(a[3]), "r"(b[0]), "r"(b[1]));
}

__device__ __forceinline__ uint64_t pack4h(__half a, __half b, __half c, __half d) {
    __half2 p0 = __halves2half2(a, b);
    __half2 p1 = __halves2half2(c, d);
    uint32_t u0 = *(uint32_t*)&p0;
    uint32_t u1 = *(uint32_t*)&p1;
    return (uint64_t)u0 | ((uint64_t)u1 << 32);
}

// ---------------- CSR build ----------------
__global__ void zero_cnt_kernel() {
    int i = blockIdx.x * 256 + threadIdx.x;
    if (i < N_TOT) { g_cnt[i] = 0; g_cur[i] = 0; }
}
__global__ void hist_kernel(const int* __restrict__ rows) {
    int i = blockIdx.x * 256 + threadIdx.x;
    if (i < E_TOT) atomicAdd(&g_cnt[rows[i]], 1);
}
__global__ void scan_kernel() {
    __shared__ int wsum[32];
    __shared__ int chunk_total;
    __shared__ int s_running;
    const int tid = threadIdx.x;
    const int lane = tid & 31, wid = tid >> 5;
    if (tid == 0) s_running = 0;
    __syncthreads();
    for (int base = 0; base < N_TOT; base += 1024) {
        int i = base + tid;
        int x = (i < N_TOT) ? g_cnt[i] : 0;
        int v = x;
        #pragma unroll
        for (int off = 1; off < 32; off <<= 1) {
            int u = __shfl_up_sync(0xffffffffu, v, off);
            if (lane >= off) v += u;
        }
        if (lane == 31) wsum[wid] = v;
        __syncthreads();
        if (wid == 0) {
            int w = wsum[lane];
            #pragma unroll
            for (int off = 1; off < 32; off <<= 1) {
                int u = __shfl_up_sync(0xffffffffu, w, off);
                if (lane >= off) w += u;
            }
            wsum[lane] = w;
            if (lane == 31) chunk_total = w;
        }
        __syncthreads();
        int warp_prefix = (wid == 0) ? 0 : wsum[wid - 1];
        int excl = s_running + warp_prefix + v - x;
        if (i < N_TOT) g_rowptr[i] = excl;
        __syncthreads();
        if (tid == 0) s_running += chunk_total;
        __syncthreads();
    }
    if (tid == 0) g_rowptr[N_TOT] = s_running;
}
__global__ void scatter_edges_kernel(const int* __restrict__ rows,
                                     const int* __restrict__ cols,
                                     const float* __restrict__ vals) {
    int i = blockIdx.x * 256 + threadIdx.x;
    if (i < E_TOT) {
        int r = rows[i];
        int pos = g_rowptr[r] + atomicAdd(&g_cur[r], 1);
        g_edges[pos] = make_int2(cols[i], __float_as_int(vals[i]));
    }
}

// ---------------- fp16 conversions ----------------
__global__ void convertA_kernel(const float* __restrict__ x,
                                const float* __restrict__ motif,
                                __half* __restrict__ out) {
    int idx = blockIdx.x * 256 + threadIdx.x;      // N_TOT*128 threads
    if (idx >= N_TOT * 128) return;
    int m  = idx >> 7;
    int kq = (idx & 127) << 2;
    const float* src = (m < N_XROWS)
        ? x + (size_t)m * 512 + kq
        : motif + (size_t)(m - N_XROWS) * 512 + kq;
    float4 v = *(const float4*)src;
    *(uint64_t*)(out + (size_t)m * 512 + kq) =
        pack4h(__float2half_rn(v.x), __float2half_rn(v.y),
               __float2half_rn(v.z), __float2half_rn(v.w));
}

// B [K,N=256] fp32 -> g_b1 [n][k] fp16 (B^T, K-major, stride K)
__global__ void convertB_kernel(const float* __restrict__ B, int K,
                                __half* __restrict__ out) {
    int idx = blockIdx.x * 256 + threadIdx.x;    // K*256 threads
    if (idx >= K * 256) return;
    int k = idx >> 8;
    int n = idx & 255;
    out[(size_t)n * K + k] = __float2half_rn(B[idx]);
}

// ---------------- HMMA GEMM: C[M,256] = A16 @ B16^T (1 pass) ----
#define SA 40                               // padded SMEM row stride (halfs)
#define STAGE_ELEMS ((128 + 256) * SA)      // A tile + B tile
#define GEMM_SMEM   (3 * STAGE_ELEMS * 2)   // 92160 bytes

__global__ void __launch_bounds__(256, 1)
hmma_gemm_kernel(const __half* __restrict__ A,
                 const __half* __restrict__ B1,
                 __half* __restrict__ C, int K, int M) {
    extern __shared__ __half sm[];
    const int t    = threadIdx.x;
    const int lane = t & 31, wid = t >> 5;
    const int wm   = wid & 1, wn = wid >> 1;   // 2 x 4 warp grid
    const int gid  = lane >> 2, tid4 = lane & 3;
    const int row0 = blockIdx.x * 128;
    const int CC = K >> 5;            // 32-wide chunks, single pass

    float acc[4][8][4];
    #pragma unroll
    for (int mi = 0; mi < 4; mi++)
        #pragma unroll
        for (int ni = 0; ni < 8; ni++)
            #pragma unroll
            for (int q = 0; q < 4; q++) acc[mi][ni][q] = 0.f;

    auto load_chunk = [&](int stage, int koff) {
        __half* s  = sm + stage * STAGE_ELEMS;
        __half* sB = s + 128 * SA;
        #pragma unroll
        for (int j = 0; j < 2; j++) {          // A: 128 rows x 32 halfs
            int u = j * 256 + t;
            int r = u >> 2, q = u & 3;
            cp_async16(smem_u32(s + r * SA + q * 8),
                       A + (size_t)(row0 + r) * K + koff + q * 8);
        }
        #pragma unroll
        for (int j = 0; j < 4; j++) {          // B: 256 rows x 32 halfs
            int u = j * 256 + t;
            int r = u >> 2, q = u & 3;
            cp_async16(smem_u32(sB + r * SA + q * 8),
                       B1 + (size_t)r * K + koff + q * 8);
        }
        CP_COMMIT();
    };

    load_chunk(0, 0);
    load_chunk(1, 32);

    for (int c = 0; c < CC; c++) {
        if (c < CC - 1) CP_WAIT(1); else CP_WAIT(0);
        __syncthreads();
        if (c + 2 < CC) load_chunk((c + 2) % 3, (c + 2) << 5);
        const __half* s  = sm + (c % 3) * STAGE_ELEMS;
        const __half* sB = s + 128 * SA;
        #pragma unroll
        for (int ks = 0; ks < 2; ks++) {
            uint32_t a[4][4], b[8][2];
            const int kc = ks * 16 + tid4 * 2;
            #pragma unroll
            for (int mi = 0; mi < 4; mi++) {
                int r0 = wm * 64 + mi * 16 + gid;
                a[mi][0] = *(const uint32_t*)(s + (size_t)r0 * SA + kc);
                a[mi][1] = *(const uint32_t*)(s + (size_t)(r0 + 8) * SA + kc);
                a[mi][2] = *(const uint32_t*)(s + (size_t)r0 * SA + kc + 8);
                a[mi][3] = *(const uint32_t*)(s + (size_t)(r0 + 8) * SA + kc + 8);
            }
            #pragma unroll
            for (int ni = 0; ni < 8; ni++) {
                int n0 = wn * 64 + ni * 8 + gid;
                b[ni][0] = *(const uint32_t*)(sB + (size_t)n0 * SA + kc);
                b[ni][1] = *(const uint32_t*)(sB + (size_t)n0 * SA + kc + 8);
            }
            #pragma unroll
            for (int mi = 0; mi < 4; mi++)
                #pragma unroll
                for (int ni = 0; ni < 8; ni++)
                    mma16816(acc[mi][ni], a[mi], b[ni]);
        }
    }

    // epilogue -> fp16
    #pragma unroll
    for (int mi = 0; mi < 4; mi++) {
        int r = row0 + wm * 64 + mi * 16 + gid;
        #pragma unroll
        for (int ni = 0; ni < 8; ni++) {
            int cidx = wn * 64 + ni * 8 + tid4 * 2;
            if (r < M)
                *(__half2*)(C + (size_t)r * 256 + cidx) =
                    __floats2half2_rn(acc[mi][ni][0], acc[mi][ni][1]);
            if (r + 8 < M)
                *(__half2*)(C + (size_t)(r + 8) * 256 + cidx) =
                    __floats2half2_rn(acc[mi][ni][2], acc[mi][ni][3]);
        }
    }
}

// ---------------- SpMM: relu(bias + sum val*support_fp16[col]) ----------
__device__ __forceinline__ void fma4(float4& acc, float v, uint2 raw) {
    float2 f0 = __half22float2(*(__half2*)&raw.x);
    float2 f1 = __half22float2(*(__half2*)&raw.y);
    acc.x = fmaf(v, f0.x, acc.x);
    acc.y = fmaf(v, f0.y, acc.y);
    acc.z = fmaf(v, f1.x, acc.z);
    acc.w = fmaf(v, f1.y, acc.w);
}

__device__ __forceinline__ float4 spmm_row(const uint2* __restrict__ sup2,
                                           int row, int t) {
    int s = g_rowptr[row];
    int e = g_rowptr[row + 1];
    float4 acc0 = make_float4(0.f, 0.f, 0.f, 0.f);
    float4 acc1 = make_float4(0.f, 0.f, 0.f, 0.f);
    int i = s;
    for (; i + 4 <= e; i += 4) {
        int2 e0 = __ldg(&g_edges[i]);
        int2 e1 = __ldg(&g_edges[i + 1]);
        int2 e2 = __ldg(&g_edges[i + 2]);
        int2 e3 = __ldg(&g_edges[i + 3]);
        uint2 r0 = __ldg(&sup2[(size_t)e0.x * 64 + t]);
        uint2 r1 = __ldg(&sup2[(size_t)e1.x * 64 + t]);
        uint2 r2 = __ldg(&sup2[(size_t)e2.x * 64 + t]);
        uint2 r3 = __ldg(&sup2[(size_t)e3.x * 64 + t]);
        fma4(acc0, __int_as_float(e0.y), r0);
        fma4(acc1, __int_as_float(e1.y), r1);
        fma4(acc0, __int_as_float(e2.y), r2);
        fma4(acc1, __int_as_float(e3.y), r3);
    }
    for (; i < e; i++) {
        int2 ed = __ldg(&g_edges[i]);
        uint2 r0 = __ldg(&sup2[(size_t)ed.x * 64 + t]);
        fma4(acc0, __int_as_float(ed.y), r0);
    }
    acc0.x += acc1.x; acc0.y += acc1.y; acc0.z += acc1.z; acc0.w += acc1.w;
    return acc0;
}

// writes next layer's fp16 A operand (stride 256)
__global__ void __launch_bounds__(64)
spmm_h16_kernel(const uint2* __restrict__ sup2,
                const float4* __restrict__ bias,
                __half* __restrict__ a_next) {
    const int row = blockIdx.x;
    const int t   = threadIdx.x;
    float4 acc = spmm_row(sup2, row, t);
    float4 b = __ldg(&bias[t]);
    float ox = fmaxf(acc.x + b.x, 0.f);
    float oy = fmaxf(acc.y + b.y, 0.f);
    float oz = fmaxf(acc.z + b.z, 0.f);
    float ow = fmaxf(acc.w + b.w, 0.f);
    *(uint64_t*)(a_next + (size_t)row * 256 + t * 4) =
        pack4h(__float2half_rn(ox), __float2half_rn(oy),
               __float2half_rn(oz), __float2half_rn(ow));
}

// Layer-3 SpMM fused with the output permutation: only rows < N_XROWS,
// writes relu(agg + b) directly at out[pos[row]].
__global__ void __launch_bounds__(64)
spmm_out_kernel(const uint2* __restrict__ sup2,
                const float4* __restrict__ bias,
                const int* __restrict__ pos,
                float4* __restrict__ out) {
    const int row = blockIdx.x;          // < N_XROWS
    const int t   = threadIdx.x;
    float4 acc = spmm_row(sup2, row, t);
    float4 b = __ldg(&bias[t]);
    float4 o;
    o.x = fmaxf(acc.x + b.x, 0.f);
    o.y = fmaxf(acc.y + b.y, 0.f);
    o.z = fmaxf(acc.z + b.z, 0.f);
    o.w = fmaxf(acc.w + b.w, 0.f);
    out[(size_t)__ldg(&pos[row]) * 64 + t] = o;
}

// ---------------- output zero ----------------
__global__ void zero_out_kernel(float4* __restrict__ out, int n4) {
    int i = blockIdx.x * 256 + threadIdx.x;
    if (i < n4) out[i] = make_float4(0.f, 0.f, 0.f, 0.f);
}

// ---------------- launch ----------------
extern "C" void kernel_launch(void* const* d_in, const int* in_sizes, int n_in,
                              void* d_out, int out_size) {
    const float* x     = (const float*)d_in[0];
    const float* motif = (const float*)d_in[1];
    const int*   rows  = (const int*)d_in[2];
    const int*   cols  = (const int*)d_in[3];
    const float* vals  = (const float*)d_in[4];
    const int*   pos   = (const int*)d_in[5];
    int wi = 6;
    if (n_in >= 13 && in_sizes[6] == 1) wi = 7;
    const float* w1 = (const float*)d_in[wi + 0];
    const float* b1 = (const float*)d_in[wi + 1];
    const float* w2 = (const float*)d_in[wi + 2];
    const float* b2 = (const float*)d_in[wi + 3];
    const float* w3 = (const float*)d_in[wi + 4];
    const float* b3 = (const float*)d_in[wi + 5];

    __half* support;
    __half *a, *bt1;
    cudaGetSymbolAddress((void**)&support, g_support);
    cudaGetSymbolAddress((void**)&a, g_a);
    cudaGetSymbolAddress((void**)&bt1, g_b1);

    cudaFuncSetAttribute(hmma_gemm_kernel,
                         cudaFuncAttributeMaxDynamicSharedMemorySize, GEMM_SMEM);

    // Side stream for the independent CSR build + output zeroing.
    // Created per call and intentionally not destroyed (destroying a forked
    // stream mid-capture would invalidate the harness's graph capture).
    cudaStream_t s2;
    cudaStreamCreateWithFlags(&s2, cudaStreamNonBlocking);
    cudaEvent_t evFork, evJoin;
    cudaEventCreateWithFlags(&evFork, cudaEventDisableTiming);
    cudaEventCreateWithFlags(&evJoin, cudaEventDisableTiming);

    // fork: side chain depends on nothing done so far on the main stream
    cudaEventRecord(evFork, 0);
    cudaStreamWaitEvent(s2, evFork, 0);

    // --- side chain (s2): CSR build + zero output ---
    zero_cnt_kernel<<<(N_TOT + 255) / 256, 256, 0, s2>>>();
    hist_kernel<<<E_TOT / 256, 256, 0, s2>>>(rows);
    scan_kernel<<<1, 1024, 0, s2>>>();
    scatter_edges_kernel<<<E_TOT / 256, 256, 0, s2>>>(rows, cols, vals);
    int n4 = out_size / 4;
    zero_out_kernel<<<(n4 + 255) / 256, 256, 0, s2>>>((float4*)d_out, n4);
    cudaEventRecord(evJoin, s2);

    const int gemm_grid = M_PAD / 128;   // 469, full-N CTAs

    // --- main chain: layer 1 dense part (K=512) ---
    convertA_kernel<<<(N_TOT * 128) / 256, 256>>>(x, motif, a);
    convertB_kernel<<<512, 256>>>(w1, 512, bt1);
    hmma_gemm_kernel<<<gemm_grid, 256, GEMM_SMEM>>>(a, bt1, support, 512, N_TOT);

    // join: SpMM needs CSR; final spmm_out also needs zeroed output
    cudaStreamWaitEvent(0, evJoin, 0);

    spmm_h16_kernel<<<N_TOT, 64>>>((const uint2*)support, (const float4*)b1, a);

    // --- layer 2 (K=256) ---
    convertB_kernel<<<256, 256>>>(w2, 256, bt1);
    hmma_gemm_kernel<<<gemm_grid, 256, GEMM_SMEM>>>(a, bt1, support, 256, N_TOT);
    spmm_h16_kernel<<<N_TOT, 64>>>((const uint2*)support, (const float4*)b2, a);

    // --- layer 3 (K=256): SpMM fused with output scatter ---
    convertB_kernel<<<256, 256>>>(w3, 256, bt1);
    hmma_gemm_kernel<<<gemm_grid, 256, GEMM_SMEM>>>(a, bt1, support, 256, N_TOT);
    spmm_out_kernel<<<N_XROWS, 64>>>((const uint2*)support, (const float4*)b3,
                                     pos, (float4*)d_out);
}

// round 9
// speedup vs baseline: 2.5649x; 1.0705x over previous
#include <cuda_runtime.h>
#include <cuda_fp16.h>
#include <cstdint>

#define N_XROWS   50000
#define N_MOTIF   10000
#define N_TOT     60000
#define E_TOT     1920000
#define NHID      256
#define PAD_N     65536
#define M_PAD     60032          // 938 * 64

// ---------------- device scratch (no allocs allowed) ----------------
__device__ int   g_cnt[N_TOT];
__device__ int   g_cur[N_TOT];
__device__ int   g_rowptr[N_TOT + 1];
__device__ int2  g_edges[E_TOT];
__device__ __half g_support[(size_t)N_TOT * NHID];     // fp16 support
__device__ __half g_a[(size_t)M_PAD * 512];            // A operand, fp16
__device__ __half g_b1[256 * 512];                     // W1^T fp16, K-major
__device__ __half g_b2[256 * 256];                     // W2^T fp16
__device__ __half g_b3[256 * 256];                     // W3^T fp16

// ================= helpers =================
__device__ __forceinline__ uint32_t smem_u32(const void* p) {
    uint32_t a;
    asm("{ .reg .u64 t; cvta.to.shared.u64 t, %1; cvt.u32.u64 %0, t; }"
        : "=r"(a) : "l"(p));
    return a;
}
__device__ __forceinline__ void cp_async16(uint32_t dst, const void* src) {
    asm volatile("cp.async.cg.shared.global [%0], [%1], 16;"
                 :: "r"(dst), "l"(__cvta_generic_to_global(src)) : "memory");
}
#define CP_COMMIT() asm volatile("cp.async.commit_group;" ::: "memory")
#define CP_WAIT(n)  asm volatile("cp.async.wait_group %0;" :: "n"(n) : "memory")

__device__ __forceinline__ void mma16816(float* d, const uint32_t* a,
                                         const uint32_t* b) {
    asm volatile(
        "mma.sync.aligned.m16n8k16.row.col.f32.f16.f16.f32 "
        "{%0,%1,%2,%3}, {%4,%5,%6,%7}, {%8,%9}, {%0,%1,%2,%3};"
        : "+f"(d[0]), "+f"(d[1]), "+f"(d[2]), "+f"(d[3])
        : "r"(a[0]), "r"(a[1]), "r"(a[2]), "r"(a[3]), "r"(b[0]), "r"(b[1]));
}

__device__ __forceinline__ uint64_t pack4h(__half a, __half b, __half c, __half d) {
    __half2 p0 = __halves2half2(a, b);
    __half2 p1 = __halves2half2(c, d);
    uint32_t u0 = *(uint32_t*)&p0;
    uint32_t u1 = *(uint32_t*)&p1;
    return (uint64_t)u0 | ((uint64_t)u1 << 32);
}

// ---------------- CSR build ----------------
__global__ void zero_cnt_kernel() {
    int i = blockIdx.x * 256 + threadIdx.x;
    if (i < N_TOT) { g_cnt[i] = 0; g_cur[i] = 0; }
}
__global__ void hist_kernel(const int* __restrict__ rows) {
    int i = blockIdx.x * 256 + threadIdx.x;
    if (i < E_TOT) atomicAdd(&g_cnt[rows[i]], 1);
}
__global__ void scan_kernel() {
    __shared__ int wsum[32];
    __shared__ int chunk_total;
    __shared__ int s_running;
    const int tid = threadIdx.x;
    const int lane = tid & 31, wid = tid >> 5;
    if (tid == 0) s_running = 0;
    __syncthreads();
    for (int base = 0; base < N_TOT; base += 1024) {
        int i = base + tid;
        int x = (i < N_TOT) ? g_cnt[i] : 0;
        int v = x;
        #pragma unroll
        for (int off = 1; off < 32; off <<= 1) {
            int u = __shfl_up_sync(0xffffffffu, v, off);
            if (lane >= off) v += u;
        }
        if (lane == 31) wsum[wid] = v;
        __syncthreads();
        if (wid == 0) {
            int w = wsum[lane];
            #pragma unroll
            for (int off = 1; off < 32; off <<= 1) {
                int u = __shfl_up_sync(0xffffffffu, w, off);
                if (lane >= off) w += u;
            }
            wsum[lane] = w;
            if (lane == 31) chunk_total = w;
        }
        __syncthreads();
        int warp_prefix = (wid == 0) ? 0 : wsum[wid - 1];
        int excl = s_running + warp_prefix + v - x;
        if (i < N_TOT) g_rowptr[i] = excl;
        __syncthreads();
        if (tid == 0) s_running += chunk_total;
        __syncthreads();
    }
    if (tid == 0) g_rowptr[N_TOT] = s_running;
}
__global__ void scatter_edges_kernel(const int* __restrict__ rows,
                                     const int* __restrict__ cols,
                                     const float* __restrict__ vals) {
    int i = blockIdx.x * 256 + threadIdx.x;
    if (i < E_TOT) {
        int r = rows[i];
        int pos = g_rowptr[r] + atomicAdd(&g_cur[r], 1);
        g_edges[pos] = make_int2(cols[i], __float_as_int(vals[i]));
    }
}

// ---------------- fp16 conversions ----------------
__global__ void convertA_kernel(const float* __restrict__ x,
                                const float* __restrict__ motif,
                                __half* __restrict__ out) {
    int idx = blockIdx.x * 256 + threadIdx.x;      // N_TOT*128 threads
    if (idx >= N_TOT * 128) return;
    int m  = idx >> 7;
    int kq = (idx & 127) << 2;
    const float* src = (m < N_XROWS)
        ? x + (size_t)m * 512 + kq
        : motif + (size_t)(m - N_XROWS) * 512 + kq;
    float4 v = *(const float4*)src;
    *(uint64_t*)(out + (size_t)m * 512 + kq) =
        pack4h(__float2half_rn(v.x), __float2half_rn(v.y),
               __float2half_rn(v.z), __float2half_rn(v.w));
}

// B [K,N=256] fp32 -> out [n][k] fp16 (B^T, K-major, stride K)
__global__ void convertB_kernel(const float* __restrict__ B, int K,
                                __half* __restrict__ out) {
    int idx = blockIdx.x * 256 + threadIdx.x;    // K*256 threads
    if (idx >= K * 256) return;
    int k = idx >> 8;
    int n = idx & 255;
    out[(size_t)n * K + k] = __float2half_rn(B[idx]);
}

// ---------------- HMMA GEMM: C[M,256] = A16 @ B16^T (1 pass) ----
// CTA tile 64x256 (full N), BK=32, 8 warps as 2(M) x 4(N), warp tile 32x64.
// 3-stage cp.async pipeline, 2 CTAs/SM, fp16 epilogue.
#define SA 40                               // padded SMEM row stride (halfs)
#define STAGE_ELEMS ((64 + 256) * SA)       // A tile + B tile (12800 halfs)
#define GEMM_SMEM   (3 * STAGE_ELEMS * 2)   // 76800 bytes

__global__ void __launch_bounds__(256, 2)
hmma_gemm_kernel(const __half* __restrict__ A,
                 const __half* __restrict__ B1,
                 __half* __restrict__ C, int K, int M) {
    extern __shared__ __half sm[];
    const int t    = threadIdx.x;
    const int lane = t & 31, wid = t >> 5;
    const int wm   = wid & 1, wn = wid >> 1;   // 2 x 4 warp grid
    const int gid  = lane >> 2, tid4 = lane & 3;
    const int row0 = blockIdx.x * 64;
    const int CC = K >> 5;            // 32-wide chunks, single pass

    float acc[2][8][4];
    #pragma unroll
    for (int mi = 0; mi < 2; mi++)
        #pragma unroll
        for (int ni = 0; ni < 8; ni++)
            #pragma unroll
            for (int q = 0; q < 4; q++) acc[mi][ni][q] = 0.f;

    auto load_chunk = [&](int stage, int koff) {
        __half* s  = sm + stage * STAGE_ELEMS;
        __half* sB = s + 64 * SA;
        {                                      // A: 64 rows x 32 halfs
            int r = t >> 2, q = t & 3;
            cp_async16(smem_u32(s + r * SA + q * 8),
                       A + (size_t)(row0 + r) * K + koff + q * 8);
        }
        #pragma unroll
        for (int j = 0; j < 4; j++) {          // B: 256 rows x 32 halfs
            int u = j * 256 + t;
            int r = u >> 2, q = u & 3;
            cp_async16(smem_u32(sB + r * SA + q * 8),
                       B1 + (size_t)r * K + koff + q * 8);
        }
        CP_COMMIT();
    };

    load_chunk(0, 0);
    load_chunk(1, 32);

    for (int c = 0; c < CC; c++) {
        if (c < CC - 1) CP_WAIT(1); else CP_WAIT(0);
        __syncthreads();
        if (c + 2 < CC) load_chunk((c + 2) % 3, (c + 2) << 5);
        const __half* s  = sm + (c % 3) * STAGE_ELEMS;
        const __half* sB = s + 64 * SA;
        #pragma unroll
        for (int ks = 0; ks < 2; ks++) {
            uint32_t a[2][4], b[8][2];
            const int kc = ks * 16 + tid4 * 2;
            #pragma unroll
            for (int mi = 0; mi < 2; mi++) {
                int r0 = wm * 32 + mi * 16 + gid;
                a[mi][0] = *(const uint32_t*)(s + (size_t)r0 * SA + kc);
                a[mi][1] = *(const uint32_t*)(s + (size_t)(r0 + 8) * SA + kc);
                a[mi][2] = *(const uint32_t*)(s + (size_t)r0 * SA + kc + 8);
                a[mi][3] = *(const uint32_t*)(s + (size_t)(r0 + 8) * SA + kc + 8);
            }
            #pragma unroll
            for (int ni = 0; ni < 8; ni++) {
                int n0 = wn * 64 + ni * 8 + gid;
                b[ni][0] = *(const uint32_t*)(sB + (size_t)n0 * SA + kc);
                b[ni][1] = *(const uint32_t*)(sB + (size_t)n0 * SA + kc + 8);
            }
            #pragma unroll
            for (int mi = 0; mi < 2; mi++)
                #pragma unroll
                for (int ni = 0; ni < 8; ni++)
                    mma16816(acc[mi][ni], a[mi], b[ni]);
        }
    }

    // epilogue -> fp16
    #pragma unroll
    for (int mi = 0; mi < 2; mi++) {
        int r = row0 + wm * 32 + mi * 16 + gid;
        #pragma unroll
        for (int ni = 0; ni < 8; ni++) {
            int cidx = wn * 64 + ni * 8 + tid4 * 2;
            if (r < M)
                *(__half2*)(C + (size_t)r * 256 + cidx) =
                    __floats2half2_rn(acc[mi][ni][0], acc[mi][ni][1]);
            if (r + 8 < M)
                *(__half2*)(C + (size_t)(r + 8) * 256 + cidx) =
                    __floats2half2_rn(acc[mi][ni][2], acc[mi][ni][3]);
        }
    }
}

// ---------------- SpMM: warp-per-row, LDG.128 gathers ----------------
// 1 warp per row; lane covers cols [8*lane, 8*lane+8) as one uint4 (8 halfs).
// Block = 256 threads = 8 rows. Edge loop unrolled x4, 2 accumulator sets.
__device__ __forceinline__ void fma8(float* acc, float v, uint4 raw) {
    float2 f0 = __half22float2(*(__half2*)&raw.x);
    float2 f1 = __half22float2(*(__half2*)&raw.y);
    float2 f2 = __half22float2(*(__half2*)&raw.z);
    float2 f3 = __half22float2(*(__half2*)&raw.w);
    acc[0] = fmaf(v, f0.x, acc[0]);
    acc[1] = fmaf(v, f0.y, acc[1]);
    acc[2] = fmaf(v, f1.x, acc[2]);
    acc[3] = fmaf(v, f1.y, acc[3]);
    acc[4] = fmaf(v, f2.x, acc[4]);
    acc[5] = fmaf(v, f2.y, acc[5]);
    acc[6] = fmaf(v, f3.x, acc[6]);
    acc[7] = fmaf(v, f3.y, acc[7]);
}

__device__ __forceinline__ void spmm_row_w(const uint4* __restrict__ sup4,
                                           int row, int lane, float* acc) {
    int s = g_rowptr[row];
    int e = g_rowptr[row + 1];
    float acc1[8];
    #pragma unroll
    for (int q = 0; q < 8; q++) { acc[q] = 0.f; acc1[q] = 0.f; }
    int i = s;
    for (; i + 4 <= e; i += 4) {
        int2 e0 = __ldg(&g_edges[i]);
        int2 e1 = __ldg(&g_edges[i + 1]);
        int2 e2 = __ldg(&g_edges[i + 2]);
        int2 e3 = __ldg(&g_edges[i + 3]);
        uint4 r0 = __ldg(&sup4[(size_t)e0.x * 32 + lane]);
        uint4 r1 = __ldg(&sup4[(size_t)e1.x * 32 + lane]);
        uint4 r2 = __ldg(&sup4[(size_t)e2.x * 32 + lane]);
        uint4 r3 = __ldg(&sup4[(size_t)e3.x * 32 + lane]);
        fma8(acc,  __int_as_float(e0.y), r0);
        fma8(acc1, __int_as_float(e1.y), r1);
        fma8(acc,  __int_as_float(e2.y), r2);
        fma8(acc1, __int_as_float(e3.y), r3);
    }
    for (; i < e; i++) {
        int2 ed = __ldg(&g_edges[i]);
        uint4 r0 = __ldg(&sup4[(size_t)ed.x * 32 + lane]);
        fma8(acc, __int_as_float(ed.y), r0);
    }
    #pragma unroll
    for (int q = 0; q < 8; q++) acc[q] += acc1[q];
}

// writes next layer's fp16 A operand (stride 256)
__global__ void __launch_bounds__(256)
spmm_h16_kernel(const uint4* __restrict__ sup4,
                const float4* __restrict__ bias,
                __half* __restrict__ a_next, int nrows) {
    const int row  = blockIdx.x * 8 + (threadIdx.x >> 5);
    const int lane = threadIdx.x & 31;
    if (row >= nrows) return;
    float acc[8];
    spmm_row_w(sup4, row, lane, acc);
    float4 b0 = __ldg(&bias[lane * 2]);
    float4 b1 = __ldg(&bias[lane * 2 + 1]);
    float v0 = fmaxf(acc[0] + b0.x, 0.f), v1 = fmaxf(acc[1] + b0.y, 0.f);
    float v2 = fmaxf(acc[2] + b0.z, 0.f), v3 = fmaxf(acc[3] + b0.w, 0.f);
    float v4 = fmaxf(acc[4] + b1.x, 0.f), v5 = fmaxf(acc[5] + b1.y, 0.f);
    float v6 = fmaxf(acc[6] + b1.z, 0.f), v7 = fmaxf(acc[7] + b1.w, 0.f);
    __half2 h0 = __floats2half2_rn(v0, v1);
    __half2 h1 = __floats2half2_rn(v2, v3);
    __half2 h2 = __floats2half2_rn(v4, v5);
    __half2 h3 = __floats2half2_rn(v6, v7);
    uint4 o;
    o.x = *(uint32_t*)&h0; o.y = *(uint32_t*)&h1;
    o.z = *(uint32_t*)&h2; o.w = *(uint32_t*)&h3;
    *(uint4*)(a_next + (size_t)row * 256 + lane * 8) = o;
}

// Layer-3 SpMM fused with the output permutation: only rows < N_XROWS,
// writes relu(agg + b) directly at out[pos[row]].
__global__ void __launch_bounds__(256)
spmm_out_kernel(const uint4* __restrict__ sup4,
                const float4* __restrict__ bias,
                const int* __restrict__ pos,
                float4* __restrict__ out, int nrows) {
    const int row  = blockIdx.x * 8 + (threadIdx.x >> 5);
    const int lane = threadIdx.x & 31;
    if (row >= nrows) return;
    float acc[8];
    spmm_row_w(sup4, row, lane, acc);
    float4 b0 = __ldg(&bias[lane * 2]);
    float4 b1 = __ldg(&bias[lane * 2 + 1]);
    float4 o0, o1;
    o0.x = fmaxf(acc[0] + b0.x, 0.f); o0.y = fmaxf(acc[1] + b0.y, 0.f);
    o0.z = fmaxf(acc[2] + b0.z, 0.f); o0.w = fmaxf(acc[3] + b0.w, 0.f);
    o1.x = fmaxf(acc[4] + b1.x, 0.f); o1.y = fmaxf(acc[5] + b1.y, 0.f);
    o1.z = fmaxf(acc[6] + b1.z, 0.f); o1.w = fmaxf(acc[7] + b1.w, 0.f);
    size_t base = (size_t)__ldg(&pos[row]) * 64 + lane * 2;
    out[base]     = o0;
    out[base + 1] = o1;
}

// ---------------- output zero ----------------
__global__ void zero_out_kernel(float4* __restrict__ out, int n4) {
    int i = blockIdx.x * 256 + threadIdx.x;
    if (i < n4) out[i] = make_float4(0.f, 0.f, 0.f, 0.f);
}

// ---------------- launch ----------------
extern "C" void kernel_launch(void* const* d_in, const int* in_sizes, int n_in,
                              void* d_out, int out_size) {
    const float* x     = (const float*)d_in[0];
    const float* motif = (const float*)d_in[1];
    const int*   rows  = (const int*)d_in[2];
    const int*   cols  = (const int*)d_in[3];
    const float* vals  = (const float*)d_in[4];
    const int*   pos   = (const int*)d_in[5];
    int wi = 6;
    if (n_in >= 13 && in_sizes[6] == 1) wi = 7;
    const float* w1 = (const float*)d_in[wi + 0];
    const float* b1 = (const float*)d_in[wi + 1];
    const float* w2 = (const float*)d_in[wi + 2];
    const float* b2 = (const float*)d_in[wi + 3];
    const float* w3 = (const float*)d_in[wi + 4];
    const float* b3 = (const float*)d_in[wi + 5];

    __half* support;
    __half *a, *bt1, *bt2, *bt3;
    cudaGetSymbolAddress((void**)&support, g_support);
    cudaGetSymbolAddress((void**)&a, g_a);
    cudaGetSymbolAddress((void**)&bt1, g_b1);
    cudaGetSymbolAddress((void**)&bt2, g_b2);
    cudaGetSymbolAddress((void**)&bt3, g_b3);

    cudaFuncSetAttribute(hmma_gemm_kernel,
                         cudaFuncAttributeMaxDynamicSharedMemorySize, GEMM_SMEM);

    // Side stream for the independent CSR build + output zeroing.
    // Created per call and intentionally not destroyed (destroying a forked
    // stream mid-capture would invalidate the harness's graph capture).
    cudaStream_t s2;
    cudaStreamCreateWithFlags(&s2, cudaStreamNonBlocking);
    cudaEvent_t evFork, evJoin;
    cudaEventCreateWithFlags(&evFork, cudaEventDisableTiming);
    cudaEventCreateWithFlags(&evJoin, cudaEventDisableTiming);

    cudaEventRecord(evFork, 0);
    cudaStreamWaitEvent(s2, evFork, 0);

    // --- side chain (s2): CSR build + zero output ---
    zero_cnt_kernel<<<(N_TOT + 255) / 256, 256, 0, s2>>>();
    hist_kernel<<<E_TOT / 256, 256, 0, s2>>>(rows);
    scan_kernel<<<1, 1024, 0, s2>>>();
    scatter_edges_kernel<<<E_TOT / 256, 256, 0, s2>>>(rows, cols, vals);
    int n4 = out_size / 4;
    zero_out_kernel<<<(n4 + 255) / 256, 256, 0, s2>>>((float4*)d_out, n4);
    cudaEventRecord(evJoin, s2);

    const int gemm_grid = M_PAD / 64;    // 938, full-N CTAs
    const int spmm_grid = (N_TOT + 7) / 8;
    const int spmo_grid = (N_XROWS + 7) / 8;

    // --- main chain: weight conversions hoisted up front ---
    convertB_kernel<<<512, 256>>>(w1, 512, bt1);
    convertB_kernel<<<256, 256>>>(w2, 256, bt2);
    convertB_kernel<<<256, 256>>>(w3, 256, bt3);
    convertA_kernel<<<(N_TOT * 128) / 256, 256>>>(x, motif, a);

    // --- layer 1 (K=512) ---
    hmma_gemm_kernel<<<gemm_grid, 256, GEMM_SMEM>>>(a, bt1, support, 512, N_TOT);

    // join: SpMM needs CSR; final spmm_out also needs zeroed output
    cudaStreamWaitEvent(0, evJoin, 0);

    spmm_h16_kernel<<<spmm_grid, 256>>>((const uint4*)support,
                                        (const float4*)b1, a, N_TOT);

    // --- layer 2 (K=256) ---
    hmma_gemm_kernel<<<gemm_grid, 256, GEMM_SMEM>>>(a, bt2, support, 256, N_TOT);
    spmm_h16_kernel<<<spmm_grid, 256>>>((const uint4*)support,
                                        (const float4*)b2, a, N_TOT);

    // --- layer 3 (K=256): SpMM fused with output scatter ---
    hmma_gemm_kernel<<<gemm_grid, 256, GEMM_SMEM>>>(a, bt3, support, 256, N_TOT);
    spmm_out_kernel<<<spmo_grid, 256>>>((const uint4*)support,
                                        (const float4*)b3, pos,
                                        (float4*)d_out, N_XROWS);
}